// round 1
// baseline (speedup 1.0000x reference)
#include <cuda_runtime.h>

// Problem constants
#define B_N 65536
#define D_N 256
#define K_N 4096
#define DECAYF 0.99f
#define OMDECAYF 0.01f
#define EPSF 1e-5f

// Output layout (concatenated float32, tuple order)
#define OFF_IDX  0
#define OFF_Q    65536
#define OFF_NS   16842752
#define OFF_LOSS 16842753
#define OFF_CS   16842754
#define OFF_E    16846850
// total 17895426

// ---------------- device scratch (no allocations allowed) ----------------
__device__ float g_embed_sum[D_N * K_N];   // [D,K] scatter-add of x
__device__ float g_counts[K_N];            // histogram of assignments
__device__ float g_enorm[K_N];             // ||e_k||^2
__device__ int   g_idx[B_N];               // argmin per row
__device__ float g_scalars[4];             // 0: loss_sum, 1: n_sum, 2: n_small

// ---------------- zero scratch (runs every launch; graph-safe) -----------
__global__ void k_zero() {
    int i = blockIdx.x * blockDim.x + threadIdx.x;
    if (i < D_N * K_N) g_embed_sum[i] = 0.0f;
    if (i < K_N) g_counts[i] = 0.0f;
    if (i < 4) g_scalars[i] = 0.0f;
}

// ---------------- ||e_k||^2 ----------------------------------------------
__global__ void k_enorm(const float* __restrict__ embed) {
    int k = blockIdx.x * blockDim.x + threadIdx.x;
    if (k >= K_N) return;
    float acc = 0.0f;
    #pragma unroll 8
    for (int d = 0; d < D_N; d++) {
        float v = embed[d * K_N + k];   // coalesced across k
        acc = fmaf(v, v, acc);
    }
    g_enorm[k] = acc;
}

// ---------------- fused GEMM + argmin -------------------------------------
// score(i,k) = ||e_k||^2 - 2 * x_i . e_k   (||x||^2 constant per row)
#define BM 128
#define BN 128
#define BD 16

__global__ __launch_bounds__(256)
void k_gemm_argmin(const float* __restrict__ x, const float* __restrict__ embed) {
    __shared__ float As[BD][BM + 1];   // +1 pad: avoid store conflicts
    __shared__ float Bs[BD][BN];
    __shared__ float rS[BM][17];
    __shared__ int   rK[BM][17];

    const int m0 = blockIdx.x * BM;
    const int tid = threadIdx.x;
    const int tx = tid & 15;           // 16 col-groups of 8
    const int ty = tid >> 4;           // 16 row-groups of 8

    float bestS[8];
    int   bestK[8];
    #pragma unroll
    for (int i = 0; i < 8; i++) { bestS[i] = 3.4e38f; bestK[i] = 0; }

    for (int n0 = 0; n0 < K_N; n0 += BN) {
        float acc[8][8];
        #pragma unroll
        for (int i = 0; i < 8; i++)
            #pragma unroll
            for (int j = 0; j < 8; j++) acc[i][j] = 0.0f;

        for (int d0 = 0; d0 < D_N; d0 += BD) {
            __syncthreads();
            // load x tile [BM x BD] -> As[c][r]
            #pragma unroll
            for (int i = tid; i < BM * BD; i += 256) {
                int r = i >> 4, c = i & 15;
                As[c][r] = x[(m0 + r) * D_N + d0 + c];
            }
            // load embed tile [BD x BN] -> Bs[c][j] (row-major, coalesced)
            #pragma unroll
            for (int i = tid; i < BD * BN; i += 256) {
                int c = i >> 7, j = i & 127;
                Bs[c][j] = embed[(d0 + c) * K_N + n0 + j];
            }
            __syncthreads();

            #pragma unroll
            for (int kk = 0; kk < BD; kk++) {
                float a[8], b[8];
                #pragma unroll
                for (int i = 0; i < 8; i++) a[i] = As[kk][ty * 8 + i];
                #pragma unroll
                for (int j = 0; j < 8; j++) b[j] = Bs[kk][tx * 8 + j];
                #pragma unroll
                for (int i = 0; i < 8; i++)
                    #pragma unroll
                    for (int j = 0; j < 8; j++)
                        acc[i][j] = fmaf(a[i], b[j], acc[i][j]);
            }
        }

        // epilogue: fold into running argmin (ties -> smaller k, like jnp.argmin)
        #pragma unroll
        for (int j = 0; j < 8; j++) {
            int k = n0 + tx * 8 + j;
            float en = g_enorm[k];
            #pragma unroll
            for (int i = 0; i < 8; i++) {
                float s = en - 2.0f * acc[i][j];
                if (s < bestS[i] || (s == bestS[i] && k < bestK[i])) {
                    bestS[i] = s; bestK[i] = k;
                }
            }
        }
    }

    // cross-thread row reduction (16 candidates per row)
    __syncthreads();
    #pragma unroll
    for (int i = 0; i < 8; i++) {
        rS[ty * 8 + i][tx] = bestS[i];
        rK[ty * 8 + i][tx] = bestK[i];
    }
    __syncthreads();
    if (tid < BM) {
        float bs = rS[tid][0];
        int   bk = rK[tid][0];
        #pragma unroll
        for (int t = 1; t < 16; t++) {
            float s = rS[tid][t];
            int   k = rK[tid][t];
            if (s < bs || (s == bs && k < bk)) { bs = s; bk = k; }
        }
        g_idx[m0 + tid] = bk;
    }
}

// ---------------- quantize + STE + loss + histogram + scatter-add ---------
__global__ __launch_bounds__(256)
void k_quant(const float* __restrict__ x, const float* __restrict__ embed,
             float* __restrict__ out) {
    __shared__ float blk_loss;
    if (threadIdx.x == 0) blk_loss = 0.0f;
    __syncthreads();

    int warp = threadIdx.x >> 5, lane = threadIdx.x & 31;
    int row = blockIdx.x * 8 + warp;
    int k = g_idx[row];
    const float* xr = x + row * D_N;
    float lacc = 0.0f;

    #pragma unroll
    for (int it = 0; it < 8; it++) {
        int d = lane + it * 32;
        float xv = xr[d];
        float ev = embed[d * K_N + k];
        float diff = ev - xv;                    // matches (quantize - x)
        out[OFF_Q + row * D_N + d] = xv + diff;  // STE: x + (q - x)
        lacc = fmaf(diff, diff, lacc);
        atomicAdd(&g_embed_sum[d * K_N + k], xv);
    }

    // warp reduce loss
    #pragma unroll
    for (int o = 16; o > 0; o >>= 1) lacc += __shfl_down_sync(0xffffffffu, lacc, o);
    if (lane == 0) {
        atomicAdd(&blk_loss, lacc);
        atomicAdd(&g_counts[k], 1.0f);
        out[OFF_IDX + row] = (float)k;
    }
    __syncthreads();
    if (threadIdx.x == 0) atomicAdd(&g_scalars[0], blk_loss);
}

// ---------------- new_cluster_size + reductions ---------------------------
__global__ void k_stats(const float* __restrict__ cluster_size,
                        float* __restrict__ out) {
    __shared__ float sSum[256], sSmall[256];
    int tid = threadIdx.x;
    int k = blockIdx.x * 256 + tid;
    float ncs = fmaf(DECAYF, cluster_size[k], OMDECAYF * g_counts[k]);
    out[OFF_CS + k] = ncs;
    sSum[tid] = ncs;
    sSmall[tid] = (ncs < 1.0f) ? 1.0f : 0.0f;
    __syncthreads();
    for (int o = 128; o > 0; o >>= 1) {
        if (tid < o) { sSum[tid] += sSum[tid + o]; sSmall[tid] += sSmall[tid + o]; }
        __syncthreads();
    }
    if (tid == 0) {
        atomicAdd(&g_scalars[1], sSum[0]);
        atomicAdd(&g_scalars[2], sSmall[0]);
    }
}

// ---------------- finalize: new_embed + scalars ---------------------------
__global__ void k_final(const float* __restrict__ embed_avg,
                        float* __restrict__ out) {
    int i = blockIdx.x * blockDim.x + threadIdx.x;
    if (i == 0) {
        out[OFF_NS]   = g_scalars[2];
        out[OFF_LOSS] = g_scalars[0] * (1.0f / ((float)B_N * (float)D_N));
    }
    if (i < D_N * K_N) {
        int k = i & (K_N - 1);
        float ncs = out[OFF_CS + k];
        float n = g_scalars[1];
        float cs = (ncs + EPSF) / (n + (float)K_N * EPSF) * n;
        float navg = fmaf(DECAYF, embed_avg[i], OMDECAYF * g_embed_sum[i]);
        out[OFF_E + i] = navg / cs;
    }
}

// ---------------- launch ---------------------------------------------------
extern "C" void kernel_launch(void* const* d_in, const int* in_sizes, int n_in,
                              void* d_out, int out_size) {
    const float* x            = (const float*)d_in[0];  // [B, D]
    const float* embed        = (const float*)d_in[1];  // [D, K]
    const float* cluster_size = (const float*)d_in[2];  // [K]
    const float* embed_avg    = (const float*)d_in[3];  // [D, K]
    float* out = (float*)d_out;

    (void)in_sizes; (void)n_in; (void)out_size;

    k_zero<<<(D_N * K_N + 255) / 256, 256>>>();
    k_enorm<<<(K_N + 255) / 256, 256>>>(embed);
    k_gemm_argmin<<<B_N / BM, 256>>>(x, embed);
    k_quant<<<B_N / 8, 256>>>(x, embed, out);
    k_stats<<<K_N / 256, 256>>>(cluster_size, out);
    k_final<<<(D_N * K_N + 255) / 256, 256>>>(embed_avg, out);
}

// round 5
// speedup vs baseline: 1.9152x; 1.9152x over previous
#include <cuda_runtime.h>
#include <cstdint>

// Problem constants
#define B_N 65536
#define D_N 256
#define K_N 4096
#define DECAYF 0.99f
#define OMDECAYF 0.01f
#define EPSF 1e-5f
#define TAU 0.25f

// Output layout (concatenated float32, tuple order)
#define OFF_IDX  0
#define OFF_Q    65536
#define OFF_NS   16842752
#define OFF_LOSS 16842753
#define OFF_CS   16842754
#define OFF_E    16846850

// ---------------- device scratch ----------------
__device__ float g_sumT[K_N * D_N];        // [K,D] scatter-add of x (transposed)
__device__ float g_embedT[K_N * D_N];      // [K,D] transposed codebook
__device__ float g_counts[K_N];
__device__ float g_enorm[K_N];
__device__ int   g_idx[B_N];
__device__ int   g_cand[B_N * 32];         // 32 candidates per row
__device__ int   g_fall[B_N];              // flagged-row worklist
__device__ int   g_nfall;
__device__ float g_scalars[4];             // 0: loss_sum, 1: n_sum, 2: n_small

// ---------------- zero scratch -----------------
__global__ void k_zero() {
    int i = blockIdx.x * blockDim.x + threadIdx.x;
    if (i < K_N * D_N) g_sumT[i] = 0.0f;
    if (i < K_N) g_counts[i] = 0.0f;
    if (i < 4) g_scalars[i] = 0.0f;
    if (i == 0) g_nfall = 0;
}

// ---------------- transpose embed [D,K] -> embedT [K,D] -------------------
__global__ void k_transp(const float* __restrict__ embed) {
    __shared__ float t[32][33];
    int bx = blockIdx.x;
    int by = blockIdx.y;
    int kx = bx * 32 + threadIdx.x;
    int dy = by * 32 + threadIdx.y;
    #pragma unroll
    for (int i = 0; i < 32; i += 8)
        t[threadIdx.y + i][threadIdx.x] = embed[(dy + i) * K_N + kx];
    __syncthreads();
    int k2 = bx * 32 + threadIdx.y;
    int d2 = by * 32 + threadIdx.x;
    #pragma unroll
    for (int i = 0; i < 32; i += 8)
        g_embedT[(k2 + i) * D_N + d2] = t[threadIdx.x][threadIdx.y + i];
}

// ---------------- ||e_k||^2 (exact fp32) ----------------------------------
__global__ void k_enorm(const float* __restrict__ embed) {
    int k = blockIdx.x * blockDim.x + threadIdx.x;
    if (k >= K_N) return;
    float acc = 0.0f;
    #pragma unroll 8
    for (int d = 0; d < D_N; d++) {
        float v = embed[d * K_N + k];
        acc = fmaf(v, v, acc);
    }
    g_enorm[k] = acc;
}

// ---------------- tf32 helpers ---------------------------------------------
__device__ __forceinline__ unsigned f2tf(float f) {
    unsigned u;
    asm("cvt.rna.tf32.f32 %0, %1;" : "=r"(u) : "f"(f));
    return u;
}

__device__ __forceinline__ void mma_tf32(float* c, const unsigned* a, const unsigned* b) {
    asm volatile(
        "mma.sync.aligned.m16n8k8.row.col.f32.tf32.tf32.f32 "
        "{%0,%1,%2,%3}, {%4,%5,%6,%7}, {%8,%9}, {%0,%1,%2,%3};\n"
        : "+f"(c[0]), "+f"(c[1]), "+f"(c[2]), "+f"(c[3])
        : "r"(a[0]), "r"(a[1]), "r"(a[2]), "r"(a[3]), "r"(b[0]), "r"(b[1]));
}

// ---------------- fused tf32 GEMM + per-thread top-2 candidates ------------
#define GBM 256
#define GBN 128
#define GBK 32
#define APAD 4
#define BPAD 4
#define SMEM_GEMM ((GBK * (GBM + APAD) + GBK * (GBN + BPAD)) * 4)

__global__ __launch_bounds__(512, 1)
void k_gemm_top2(const float* __restrict__ x, const float* __restrict__ embed) {
    extern __shared__ __align__(16) unsigned char raw[];
    unsigned (*As)[GBM + APAD] = reinterpret_cast<unsigned(*)[GBM + APAD]>(raw);
    unsigned (*Bs)[GBN + BPAD] =
        reinterpret_cast<unsigned(*)[GBN + BPAD]>(raw + GBK * (GBM + APAD) * 4);
    __shared__ float sEn[GBN];

    const int tid = threadIdx.x;
    const int m0 = blockIdx.x * GBM;
    const int warp = tid >> 5, lane = tid & 31;
    const int wm = warp >> 2, wn = warp & 3;
    const int g = lane >> 2, q = lane & 3;

    float t1s[8], t2s[8];
    unsigned pk[8];
    #pragma unroll
    for (int i = 0; i < 8; i++) { t1s[i] = 3.4e38f; t2s[i] = 3.4e38f; pk[i] = 0; }

    for (int n0 = 0; n0 < K_N; n0 += GBN) {
        float acc[4][4][4];
        #pragma unroll
        for (int a = 0; a < 4; a++)
            #pragma unroll
            for (int b = 0; b < 4; b++)
                #pragma unroll
                for (int c = 0; c < 4; c++) acc[a][b][c] = 0.0f;

        for (int d0 = 0; d0 < D_N; d0 += GBK) {
            __syncthreads();
            if (d0 == 0 && tid < GBN) sEn[tid] = g_enorm[n0 + tid];
            #pragma unroll
            for (int i = tid; i < GBM * GBK / 4; i += 512) {
                int r = i >> 3, c4 = i & 7;
                float4 v = *reinterpret_cast<const float4*>(
                    x + (m0 + r) * D_N + d0 + c4 * 4);
                As[c4 * 4 + 0][r] = f2tf(v.x);
                As[c4 * 4 + 1][r] = f2tf(v.y);
                As[c4 * 4 + 2][r] = f2tf(v.z);
                As[c4 * 4 + 3][r] = f2tf(v.w);
            }
            #pragma unroll
            for (int i = tid; i < GBK * GBN / 4; i += 512) {
                int kk = i >> 5, j4 = i & 31;
                float4 v = *reinterpret_cast<const float4*>(
                    embed + (d0 + kk) * K_N + n0 + j4 * 4);
                uint4 w = make_uint4(f2tf(v.x), f2tf(v.y), f2tf(v.z), f2tf(v.w));
                *reinterpret_cast<uint4*>(&Bs[kk][j4 * 4]) = w;
            }
            __syncthreads();

            #pragma unroll
            for (int k0 = 0; k0 < GBK; k0 += 8) {
                unsigned a[4][4], b[4][2];
                #pragma unroll
                for (int mf = 0; mf < 4; mf++) {
                    int mr = wm * 64 + mf * 16 + g;
                    a[mf][0] = As[k0 + q][mr];
                    a[mf][1] = As[k0 + q][mr + 8];
                    a[mf][2] = As[k0 + q + 4][mr];
                    a[mf][3] = As[k0 + q + 4][mr + 8];
                }
                #pragma unroll
                for (int nf = 0; nf < 4; nf++) {
                    int nc = wn * 32 + nf * 8 + g;
                    b[nf][0] = Bs[k0 + q][nc];
                    b[nf][1] = Bs[k0 + q + 4][nc];
                }
                #pragma unroll
                for (int mf = 0; mf < 4; mf++)
                    #pragma unroll
                    for (int nf = 0; nf < 4; nf++)
                        mma_tf32(acc[mf][nf], a[mf], b[nf]);
            }
        }

        #pragma unroll
        for (int nf = 0; nf < 4; nf++) {
            #pragma unroll
            for (int e = 0; e < 2; e++) {
                int col = wn * 32 + nf * 8 + 2 * q + e;
                float en = sEn[col];
                int k = n0 + col;
                #pragma unroll
                for (int mf = 0; mf < 4; mf++) {
                    #pragma unroll
                    for (int h = 0; h < 2; h++) {
                        float s = fmaf(-2.0f, acc[mf][nf][h * 2 + e], en);
                        int rid = mf * 2 + h;
                        if (s < t1s[rid]) {
                            t2s[rid] = t1s[rid];
                            t1s[rid] = s;
                            pk[rid] = ((pk[rid] & 0xffffu) << 16) | (unsigned)k;
                        } else if (s < t2s[rid]) {
                            t2s[rid] = s;
                            pk[rid] = (pk[rid] & 0xffffu) | ((unsigned)k << 16);
                        }
                    }
                }
            }
        }
    }

    const int slot = (wn * 4 + q) * 2;
    #pragma unroll
    for (int rid = 0; rid < 8; rid++) {
        int mf = rid >> 1, h = rid & 1;
        int row = m0 + wm * 64 + mf * 16 + h * 8 + g;
        g_cand[row * 32 + slot + 0] = (int)(pk[rid] & 0xffffu);
        g_cand[row * 32 + slot + 1] = (int)(pk[rid] >> 16);
    }
}

// ---------------- exact rescore (32 cands) + gap-certification -------------
// If the true argmin was evicted from the candidate set by tf32 noise, the
// surviving top-2 exact gap is provably <= 2*noise. Gap >= TAU certifies the
// pick; otherwise the row goes to the full-scan fallback.
__global__ __launch_bounds__(256)
void k_assign(const float* __restrict__ x) {
    int warp = threadIdx.x >> 5, lane = threadIdx.x & 31;
    int row = blockIdx.x * 8 + warp;
    const float4* xr = reinterpret_cast<const float4*>(x + row * D_N);
    float4 xa = xr[lane * 2], xb = xr[lane * 2 + 1];
    const int* cand = g_cand + row * 32;

    float bs = 3.4e38f, bs2 = 3.4e38f; int bk = 1 << 30;
    #pragma unroll 4
    for (int c = 0; c < 32; c++) {
        int k = cand[c];
        const float4* er = reinterpret_cast<const float4*>(g_embedT + k * D_N);
        float4 ea = er[lane * 2], eb = er[lane * 2 + 1];
        float dot = 0.0f;
        dot = fmaf(xa.x, ea.x, dot); dot = fmaf(xa.y, ea.y, dot);
        dot = fmaf(xa.z, ea.z, dot); dot = fmaf(xa.w, ea.w, dot);
        dot = fmaf(xb.x, eb.x, dot); dot = fmaf(xb.y, eb.y, dot);
        dot = fmaf(xb.z, eb.z, dot); dot = fmaf(xb.w, eb.w, dot);
        #pragma unroll
        for (int o = 16; o > 0; o >>= 1) dot += __shfl_xor_sync(0xffffffffu, dot, o);
        float s = fmaf(-2.0f, dot, g_enorm[k]);
        if (s < bs || (s == bs && k < bk)) { bs2 = bs; bs = s; bk = k; }
        else if (s < bs2) bs2 = s;
    }
    if (lane == 0) {
        g_idx[row] = bk;
        if (bs2 - bs < TAU) {
            int pos = atomicAdd(&g_nfall, 1);
            g_fall[pos] = row;
        }
    }
}

// ---------------- full exact scan for flagged rows -------------------------
// Sequential-d fp32 fma chain per code (same accumulation style as the
// round-1 kernel that passed at 2.4e-7). Coalesced over k via embed [D,K].
__global__ __launch_bounds__(256)
void k_fallback(const float* __restrict__ x, const float* __restrict__ embed) {
    __shared__ float xs[D_N];
    __shared__ float rS[8];
    __shared__ int   rK[8];
    int tid = threadIdx.x, lane = tid & 31, warp = tid >> 5;
    int n = g_nfall;
    for (int w = blockIdx.x; w < n; w += gridDim.x) {
        int row = g_fall[w];
        __syncthreads();
        xs[tid] = x[row * D_N + tid];
        __syncthreads();

        float acc[16];
        #pragma unroll
        for (int j = 0; j < 16; j++) acc[j] = 0.0f;
        for (int d = 0; d < D_N; d++) {
            float xd = xs[d];
            const float* er = embed + d * K_N + tid;
            #pragma unroll
            for (int j = 0; j < 16; j++)
                acc[j] = fmaf(xd, er[j * 256], acc[j]);
        }
        float bs = 3.4e38f; int bk = 1 << 30;
        #pragma unroll
        for (int j = 0; j < 16; j++) {
            int k = tid + j * 256;
            float s = fmaf(-2.0f, acc[j], g_enorm[k]);
            if (s < bs || (s == bs && k < bk)) { bs = s; bk = k; }
        }
        #pragma unroll
        for (int o = 16; o > 0; o >>= 1) {
            float os = __shfl_down_sync(0xffffffffu, bs, o);
            int   ok = __shfl_down_sync(0xffffffffu, bk, o);
            if (os < bs || (os == bs && ok < bk)) { bs = os; bk = ok; }
        }
        if (lane == 0) { rS[warp] = bs; rK[warp] = bk; }
        __syncthreads();
        if (tid == 0) {
            float fbs = rS[0]; int fbk = rK[0];
            #pragma unroll
            for (int t = 1; t < 8; t++) {
                if (rS[t] < fbs || (rS[t] == fbs && rK[t] < fbk)) {
                    fbs = rS[t]; fbk = rK[t];
                }
            }
            g_idx[row] = fbk;
        }
    }
}

// ---------------- quantize + STE + loss + histogram + scatter-add ---------
__global__ __launch_bounds__(256)
void k_quant(const float* __restrict__ x, float* __restrict__ out) {
    __shared__ float blk_loss;
    if (threadIdx.x == 0) blk_loss = 0.0f;
    __syncthreads();

    int warp = threadIdx.x >> 5, lane = threadIdx.x & 31;
    int row = blockIdx.x * 8 + warp;
    int k = g_idx[row];
    const float4* xr = reinterpret_cast<const float4*>(x + row * D_N);
    const float4* er = reinterpret_cast<const float4*>(g_embedT + k * D_N);
    float4* outr = reinterpret_cast<float4*>(out + OFF_Q + row * D_N);
    float lacc = 0.0f;

    #pragma unroll
    for (int it = 0; it < 2; it++) {
        int c4 = lane * 2 + it;
        float4 xv = xr[c4];
        float4 ev = er[c4];
        float d0 = ev.x - xv.x, d1 = ev.y - xv.y, d2 = ev.z - xv.z, d3 = ev.w - xv.w;
        outr[c4] = make_float4(xv.x + d0, xv.y + d1, xv.z + d2, xv.w + d3);
        lacc = fmaf(d0, d0, lacc); lacc = fmaf(d1, d1, lacc);
        lacc = fmaf(d2, d2, lacc); lacc = fmaf(d3, d3, lacc);
        int d = c4 * 4;
        atomicAdd(&g_sumT[k * D_N + d + 0], xv.x);
        atomicAdd(&g_sumT[k * D_N + d + 1], xv.y);
        atomicAdd(&g_sumT[k * D_N + d + 2], xv.z);
        atomicAdd(&g_sumT[k * D_N + d + 3], xv.w);
    }
    #pragma unroll
    for (int o = 16; o > 0; o >>= 1) lacc += __shfl_down_sync(0xffffffffu, lacc, o);
    if (lane == 0) {
        atomicAdd(&blk_loss, lacc);
        atomicAdd(&g_counts[k], 1.0f);
        out[OFF_IDX + row] = (float)k;
    }
    __syncthreads();
    if (threadIdx.x == 0) atomicAdd(&g_scalars[0], blk_loss);
}

// ---------------- new_cluster_size + reductions ---------------------------
__global__ void k_stats(const float* __restrict__ cluster_size,
                        float* __restrict__ out) {
    __shared__ float sSum[256], sSmall[256];
    int tid = threadIdx.x;
    int k = blockIdx.x * 256 + tid;
    float ncs = fmaf(DECAYF, cluster_size[k], OMDECAYF * g_counts[k]);
    out[OFF_CS + k] = ncs;
    sSum[tid] = ncs;
    sSmall[tid] = (ncs < 1.0f) ? 1.0f : 0.0f;
    __syncthreads();
    for (int o = 128; o > 0; o >>= 1) {
        if (tid < o) { sSum[tid] += sSum[tid + o]; sSmall[tid] += sSmall[tid + o]; }
        __syncthreads();
    }
    if (tid == 0) {
        atomicAdd(&g_scalars[1], sSum[0]);
        atomicAdd(&g_scalars[2], sSmall[0]);
    }
}

// ---------------- finalize: new_embed + scalars ---------------------------
__global__ void k_final(const float* __restrict__ embed_avg,
                        float* __restrict__ out) {
    int i = blockIdx.x * blockDim.x + threadIdx.x;
    if (i == 0) {
        out[OFF_NS]   = g_scalars[2];
        out[OFF_LOSS] = g_scalars[0] * (1.0f / ((float)B_N * (float)D_N));
    }
    if (i < D_N * K_N) {
        int k = i & (K_N - 1);
        int d = i >> 12;
        float ncs = out[OFF_CS + k];
        float n = g_scalars[1];
        float cs = (ncs + EPSF) / (n + (float)K_N * EPSF) * n;
        float navg = fmaf(DECAYF, embed_avg[i], OMDECAYF * g_sumT[k * D_N + d]);
        out[OFF_E + i] = navg / cs;
    }
}

// ---------------- launch ---------------------------------------------------
extern "C" void kernel_launch(void* const* d_in, const int* in_sizes, int n_in,
                              void* d_out, int out_size) {
    const float* x            = (const float*)d_in[0];  // [B, D]
    const float* embed        = (const float*)d_in[1];  // [D, K]
    const float* cluster_size = (const float*)d_in[2];  // [K]
    const float* embed_avg    = (const float*)d_in[3];  // [D, K]
    float* out = (float*)d_out;
    (void)in_sizes; (void)n_in; (void)out_size;

    static int smem_set = 0;
    if (!smem_set) {
        cudaFuncSetAttribute(k_gemm_top2,
                             cudaFuncAttributeMaxDynamicSharedMemorySize, SMEM_GEMM);
        smem_set = 1;
    }

    k_zero<<<(K_N * D_N + 255) / 256, 256>>>();
    k_transp<<<dim3(K_N / 32, D_N / 32), dim3(32, 8)>>>(embed);
    k_enorm<<<(K_N + 255) / 256, 256>>>(embed);
    k_gemm_top2<<<B_N / GBM, 512, SMEM_GEMM>>>(x, embed);
    k_assign<<<B_N / 8, 256>>>(x);
    k_fallback<<<1024, 256>>>(x, embed);
    k_quant<<<B_N / 8, 256>>>(x, out);
    k_stats<<<K_N / 256, 256>>>(cluster_size, out);
    k_final<<<(D_N * K_N + 255) / 256, 256>>>(embed_avg, out);
}

// round 6
// speedup vs baseline: 2.2883x; 1.1948x over previous
#include <cuda_runtime.h>
#include <cstdint>

// Problem constants
#define B_N 65536
#define D_N 256
#define K_N 4096
#define DECAYF 0.99f
#define OMDECAYF 0.01f
#define EPSF 1e-5f
#define TAU 0.25f

// Output layout (concatenated float32, tuple order)
#define OFF_IDX  0
#define OFF_Q    65536
#define OFF_NS   16842752
#define OFF_LOSS 16842753
#define OFF_CS   16842754
#define OFF_E    16846850

// ---------------- device scratch ----------------
__device__ float g_sumT[K_N * D_N];        // [K,D] scatter-add of x (transposed)
__device__ float g_embedT[K_N * D_N];      // [K,D] transposed codebook
__device__ float g_counts[K_N];
__device__ float g_enorm[K_N];
__device__ int   g_idx[B_N];
__device__ int   g_cand[B_N * 32];         // 32 candidates per row
__device__ int   g_fall[B_N];              // flagged-row worklist
__device__ int   g_nfall;
__device__ float g_scalars[4];             // 0: loss_sum, 1: n_sum, 2: n_small

// ---------------- zero scratch -----------------
__global__ void k_zero() {
    int i = blockIdx.x * blockDim.x + threadIdx.x;
    if (i < K_N * D_N) g_sumT[i] = 0.0f;
    if (i < K_N) g_counts[i] = 0.0f;
    if (i < 4) g_scalars[i] = 0.0f;
    if (i == 0) g_nfall = 0;
}

// ---------------- transpose embed [D,K] -> embedT [K,D] -------------------
__global__ void k_transp(const float* __restrict__ embed) {
    __shared__ float t[32][33];
    int bx = blockIdx.x;
    int by = blockIdx.y;
    int kx = bx * 32 + threadIdx.x;
    int dy = by * 32 + threadIdx.y;
    #pragma unroll
    for (int i = 0; i < 32; i += 8)
        t[threadIdx.y + i][threadIdx.x] = embed[(dy + i) * K_N + kx];
    __syncthreads();
    int k2 = bx * 32 + threadIdx.y;
    int d2 = by * 32 + threadIdx.x;
    #pragma unroll
    for (int i = 0; i < 32; i += 8)
        g_embedT[(k2 + i) * D_N + d2] = t[threadIdx.x][threadIdx.y + i];
}

// ---------------- ||e_k||^2 (exact fp32) ----------------------------------
__global__ void k_enorm(const float* __restrict__ embed) {
    int k = blockIdx.x * blockDim.x + threadIdx.x;
    if (k >= K_N) return;
    float acc = 0.0f;
    #pragma unroll 8
    for (int d = 0; d < D_N; d++) {
        float v = embed[d * K_N + k];
        acc = fmaf(v, v, acc);
    }
    g_enorm[k] = acc;
}

// ---------------- mma helper ------------------------------------------------
__device__ __forceinline__ void mma_tf32(float* c, const unsigned* a, const unsigned* b) {
    asm volatile(
        "mma.sync.aligned.m16n8k8.row.col.f32.tf32.tf32.f32 "
        "{%0,%1,%2,%3}, {%4,%5,%6,%7}, {%8,%9}, {%0,%1,%2,%3};\n"
        : "+f"(c[0]), "+f"(c[1]), "+f"(c[2]), "+f"(c[3])
        : "r"(a[0]), "r"(a[1]), "r"(a[2]), "r"(a[3]), "r"(b[0]), "r"(b[1]));
}

__device__ __forceinline__ void cp16(unsigned dst, const void* src) {
    asm volatile("cp.async.ca.shared.global [%0], [%1], 16;\n" :: "r"(dst), "l"(src));
}
__device__ __forceinline__ void cp_commit() {
    asm volatile("cp.async.commit_group;\n");
}
template <int N>
__device__ __forceinline__ void cp_wait() {
    asm volatile("cp.async.wait_group %0;\n" :: "n"(N));
}

// ---------------- fused tf32 GEMM (cp.async double-buffered) ---------------
// score(i,k) = ||e_k||^2 - 2 * x_i . e_k (tf32 ranking; exact rescore later)
#define GBM 256
#define GBN 128
#define GBK 32
#define AROW 36                 // GBK + 4 floats pad (16B multiple)
#define BROW 132                // GBN + 4 floats pad (16B multiple)
#define ABYTES (GBM * AROW * 4)
#define BBYTES (GBK * BROW * 4)
#define STAGE_BYTES (ABYTES + BBYTES)
#define SMEM_GEMM (2 * STAGE_BYTES)

__global__ __launch_bounds__(512, 1)
void k_gemm_top2(const float* __restrict__ x, const float* __restrict__ embed) {
    extern __shared__ __align__(16) unsigned char raw[];
    __shared__ float sEn[GBN];

    const int tid = threadIdx.x;
    const int m0 = blockIdx.x * GBM;
    const int warp = tid >> 5, lane = tid & 31;
    const int wm = warp >> 2, wn = warp & 3;   // 4x4 warp grid, warp tile 64x32
    const int g = lane >> 2, q = lane & 3;

    const unsigned smem_u32 = (unsigned)__cvta_generic_to_shared(raw);
    // buffer s: A at s*STAGE_BYTES, B at s*STAGE_BYTES + ABYTES
    float* Af[2] = { reinterpret_cast<float*>(raw),
                     reinterpret_cast<float*>(raw + STAGE_BYTES) };
    float* Bf[2] = { reinterpret_cast<float*>(raw + ABYTES),
                     reinterpret_cast<float*>(raw + STAGE_BYTES + ABYTES) };

    float t1s[8], t2s[8];
    unsigned pk[8];
    #pragma unroll
    for (int i = 0; i < 8; i++) { t1s[i] = 3.4e38f; t2s[i] = 3.4e38f; pk[i] = 0; }

    const int NSTAGE = D_N / GBK;   // 8

    for (int n0 = 0; n0 < K_N; n0 += GBN) {
        float acc[4][4][4];
        #pragma unroll
        for (int a = 0; a < 4; a++)
            #pragma unroll
            for (int b = 0; b < 4; b++)
                #pragma unroll
                for (int c = 0; c < 4; c++) acc[a][b][c] = 0.0f;

        if (tid < GBN) sEn[tid] = g_enorm[n0 + tid];

        // ---- issue loads for a stage into buffer `buf` ----
        auto load_stage = [&](int buf, int d0) {
            unsigned abase = smem_u32 + buf * STAGE_BYTES;
            unsigned bbase = abase + ABYTES;
            // A: GBM x GBK floats = 2048 16B chunks
            #pragma unroll
            for (int i = tid; i < GBM * GBK / 4; i += 512) {
                int r = i >> 3, c4 = i & 7;
                cp16(abase + (r * AROW + c4 * 4) * 4,
                     x + (m0 + r) * D_N + d0 + c4 * 4);
            }
            // B: GBK x GBN floats = 1024 16B chunks
            #pragma unroll
            for (int i = tid; i < GBK * GBN / 4; i += 512) {
                int kk = i >> 5, j4 = i & 31;
                cp16(bbase + (kk * BROW + j4 * 4) * 4,
                     embed + (d0 + kk) * K_N + n0 + j4 * 4);
            }
            cp_commit();
        };

        load_stage(0, 0);
        for (int s = 0; s < NSTAGE; s++) {
            if (s + 1 < NSTAGE) {
                load_stage((s + 1) & 1, (s + 1) * GBK);
                cp_wait<1>();
            } else {
                cp_wait<0>();
            }
            __syncthreads();

            const float* As = Af[s & 1];
            const float* Bs = Bf[s & 1];
            #pragma unroll
            for (int k0 = 0; k0 < GBK; k0 += 8) {
                unsigned a[4][4], b[4][2];
                #pragma unroll
                for (int mf = 0; mf < 4; mf++) {
                    int mr = wm * 64 + mf * 16 + g;
                    a[mf][0] = __float_as_uint(As[mr * AROW + k0 + q]);
                    a[mf][1] = __float_as_uint(As[(mr + 8) * AROW + k0 + q]);
                    a[mf][2] = __float_as_uint(As[mr * AROW + k0 + q + 4]);
                    a[mf][3] = __float_as_uint(As[(mr + 8) * AROW + k0 + q + 4]);
                }
                #pragma unroll
                for (int nf = 0; nf < 4; nf++) {
                    int nc = wn * 32 + nf * 8 + g;
                    b[nf][0] = __float_as_uint(Bs[(k0 + q) * BROW + nc]);
                    b[nf][1] = __float_as_uint(Bs[(k0 + q + 4) * BROW + nc]);
                }
                #pragma unroll
                for (int mf = 0; mf < 4; mf++)
                    #pragma unroll
                    for (int nf = 0; nf < 4; nf++)
                        mma_tf32(acc[mf][nf], a[mf], b[nf]);
            }
            __syncthreads();   // all reads done before next-next stage overwrites
        }

        // fold scores into per-thread top-2
        #pragma unroll
        for (int nf = 0; nf < 4; nf++) {
            #pragma unroll
            for (int e = 0; e < 2; e++) {
                int col = wn * 32 + nf * 8 + 2 * q + e;
                float en = sEn[col];
                int k = n0 + col;
                #pragma unroll
                for (int mf = 0; mf < 4; mf++) {
                    #pragma unroll
                    for (int h = 0; h < 2; h++) {
                        float s = fmaf(-2.0f, acc[mf][nf][h * 2 + e], en);
                        int rid = mf * 2 + h;
                        if (s < t1s[rid]) {
                            t2s[rid] = t1s[rid];
                            t1s[rid] = s;
                            pk[rid] = ((pk[rid] & 0xffffu) << 16) | (unsigned)k;
                        } else if (s < t2s[rid]) {
                            t2s[rid] = s;
                            pk[rid] = (pk[rid] & 0xffffu) | ((unsigned)k << 16);
                        }
                    }
                }
            }
        }
    }

    const int slot = (wn * 4 + q) * 2;
    #pragma unroll
    for (int rid = 0; rid < 8; rid++) {
        int mf = rid >> 1, h = rid & 1;
        int row = m0 + wm * 64 + mf * 16 + h * 8 + g;
        g_cand[row * 32 + slot + 0] = (int)(pk[rid] & 0xffffu);
        g_cand[row * 32 + slot + 1] = (int)(pk[rid] >> 16);
    }
}

// ---------------- exact rescore (32 cands) + gap-certification -------------
__global__ __launch_bounds__(256)
void k_assign(const float* __restrict__ x) {
    int warp = threadIdx.x >> 5, lane = threadIdx.x & 31;
    int row = blockIdx.x * 8 + warp;
    const float4* xr = reinterpret_cast<const float4*>(x + row * D_N);
    float4 xa = xr[lane * 2], xb = xr[lane * 2 + 1];
    const int* cand = g_cand + row * 32;

    float bs = 3.4e38f, bs2 = 3.4e38f; int bk = 1 << 30;
    #pragma unroll 4
    for (int c = 0; c < 32; c++) {
        int k = cand[c];
        const float4* er = reinterpret_cast<const float4*>(g_embedT + k * D_N);
        float4 ea = er[lane * 2], eb = er[lane * 2 + 1];
        float dot = 0.0f;
        dot = fmaf(xa.x, ea.x, dot); dot = fmaf(xa.y, ea.y, dot);
        dot = fmaf(xa.z, ea.z, dot); dot = fmaf(xa.w, ea.w, dot);
        dot = fmaf(xb.x, eb.x, dot); dot = fmaf(xb.y, eb.y, dot);
        dot = fmaf(xb.z, eb.z, dot); dot = fmaf(xb.w, eb.w, dot);
        #pragma unroll
        for (int o = 16; o > 0; o >>= 1) dot += __shfl_xor_sync(0xffffffffu, dot, o);
        float s = fmaf(-2.0f, dot, g_enorm[k]);
        if (s < bs || (s == bs && k < bk)) { bs2 = bs; bs = s; bk = k; }
        else if (s < bs2) bs2 = s;
    }
    if (lane == 0) {
        g_idx[row] = bk;
        if (bs2 - bs < TAU) {
            int pos = atomicAdd(&g_nfall, 1);
            g_fall[pos] = row;
        }
    }
}

// ---------------- full exact scan for flagged rows -------------------------
__global__ __launch_bounds__(256)
void k_fallback(const float* __restrict__ x, const float* __restrict__ embed) {
    __shared__ float xs[D_N];
    __shared__ float rS[8];
    __shared__ int   rK[8];
    int tid = threadIdx.x, lane = tid & 31, warp = tid >> 5;
    int n = g_nfall;
    for (int w = blockIdx.x; w < n; w += gridDim.x) {
        int row = g_fall[w];
        __syncthreads();
        xs[tid] = x[row * D_N + tid];
        __syncthreads();

        float acc[16];
        #pragma unroll
        for (int j = 0; j < 16; j++) acc[j] = 0.0f;
        for (int d = 0; d < D_N; d++) {
            float xd = xs[d];
            const float* er = embed + d * K_N + tid;
            #pragma unroll
            for (int j = 0; j < 16; j++)
                acc[j] = fmaf(xd, er[j * 256], acc[j]);
        }
        float bs = 3.4e38f; int bk = 1 << 30;
        #pragma unroll
        for (int j = 0; j < 16; j++) {
            int k = tid + j * 256;
            float s = fmaf(-2.0f, acc[j], g_enorm[k]);
            if (s < bs || (s == bs && k < bk)) { bs = s; bk = k; }
        }
        #pragma unroll
        for (int o = 16; o > 0; o >>= 1) {
            float os = __shfl_down_sync(0xffffffffu, bs, o);
            int   ok = __shfl_down_sync(0xffffffffu, bk, o);
            if (os < bs || (os == bs && ok < bk)) { bs = os; bk = ok; }
        }
        if (lane == 0) { rS[warp] = bs; rK[warp] = bk; }
        __syncthreads();
        if (tid == 0) {
            float fbs = rS[0]; int fbk = rK[0];
            #pragma unroll
            for (int t = 1; t < 8; t++) {
                if (rS[t] < fbs || (rS[t] == fbs && rK[t] < fbk)) {
                    fbs = rS[t]; fbk = rK[t];
                }
            }
            g_idx[row] = fbk;
        }
    }
}

// ---------------- quantize + STE + loss + histogram + scatter-add ---------
__global__ __launch_bounds__(256)
void k_quant(const float* __restrict__ x, float* __restrict__ out) {
    __shared__ float blk_loss;
    if (threadIdx.x == 0) blk_loss = 0.0f;
    __syncthreads();

    int warp = threadIdx.x >> 5, lane = threadIdx.x & 31;
    int row = blockIdx.x * 8 + warp;
    int k = g_idx[row];
    const float4* xr = reinterpret_cast<const float4*>(x + row * D_N);
    const float4* er = reinterpret_cast<const float4*>(g_embedT + k * D_N);
    float4* outr = reinterpret_cast<float4*>(out + OFF_Q + row * D_N);
    float lacc = 0.0f;

    #pragma unroll
    for (int it = 0; it < 2; it++) {
        int c4 = lane * 2 + it;
        float4 xv = xr[c4];
        float4 ev = er[c4];
        float d0 = ev.x - xv.x, d1 = ev.y - xv.y, d2 = ev.z - xv.z, d3 = ev.w - xv.w;
        outr[c4] = make_float4(xv.x + d0, xv.y + d1, xv.z + d2, xv.w + d3);
        lacc = fmaf(d0, d0, lacc); lacc = fmaf(d1, d1, lacc);
        lacc = fmaf(d2, d2, lacc); lacc = fmaf(d3, d3, lacc);
        int d = c4 * 4;
        atomicAdd(&g_sumT[k * D_N + d + 0], xv.x);
        atomicAdd(&g_sumT[k * D_N + d + 1], xv.y);
        atomicAdd(&g_sumT[k * D_N + d + 2], xv.z);
        atomicAdd(&g_sumT[k * D_N + d + 3], xv.w);
    }
    #pragma unroll
    for (int o = 16; o > 0; o >>= 1) lacc += __shfl_down_sync(0xffffffffu, lacc, o);
    if (lane == 0) {
        atomicAdd(&blk_loss, lacc);
        atomicAdd(&g_counts[k], 1.0f);
        out[OFF_IDX + row] = (float)k;
    }
    __syncthreads();
    if (threadIdx.x == 0) atomicAdd(&g_scalars[0], blk_loss);
}

// ---------------- new_cluster_size + reductions ---------------------------
__global__ void k_stats(const float* __restrict__ cluster_size,
                        float* __restrict__ out) {
    __shared__ float sSum[256], sSmall[256];
    int tid = threadIdx.x;
    int k = blockIdx.x * 256 + tid;
    float ncs = fmaf(DECAYF, cluster_size[k], OMDECAYF * g_counts[k]);
    out[OFF_CS + k] = ncs;
    sSum[tid] = ncs;
    sSmall[tid] = (ncs < 1.0f) ? 1.0f : 0.0f;
    __syncthreads();
    for (int o = 128; o > 0; o >>= 1) {
        if (tid < o) { sSum[tid] += sSum[tid + o]; sSmall[tid] += sSmall[tid + o]; }
        __syncthreads();
    }
    if (tid == 0) {
        atomicAdd(&g_scalars[1], sSum[0]);
        atomicAdd(&g_scalars[2], sSmall[0]);
    }
}

// ---------------- finalize: new_embed + scalars ---------------------------
__global__ void k_final(const float* __restrict__ embed_avg,
                        float* __restrict__ out) {
    int i = blockIdx.x * blockDim.x + threadIdx.x;
    if (i == 0) {
        out[OFF_NS]   = g_scalars[2];
        out[OFF_LOSS] = g_scalars[0] * (1.0f / ((float)B_N * (float)D_N));
    }
    if (i < D_N * K_N) {
        int k = i & (K_N - 1);
        int d = i >> 12;
        float ncs = out[OFF_CS + k];
        float n = g_scalars[1];
        float cs = (ncs + EPSF) / (n + (float)K_N * EPSF) * n;
        float navg = fmaf(DECAYF, embed_avg[i], OMDECAYF * g_sumT[k * D_N + d]);
        out[OFF_E + i] = navg / cs;
    }
}

// ---------------- launch ---------------------------------------------------
extern "C" void kernel_launch(void* const* d_in, const int* in_sizes, int n_in,
                              void* d_out, int out_size) {
    const float* x            = (const float*)d_in[0];  // [B, D]
    const float* embed        = (const float*)d_in[1];  // [D, K]
    const float* cluster_size = (const float*)d_in[2];  // [K]
    const float* embed_avg    = (const float*)d_in[3];  // [D, K]
    float* out = (float*)d_out;
    (void)in_sizes; (void)n_in; (void)out_size;

    static int smem_set = 0;
    if (!smem_set) {
        cudaFuncSetAttribute(k_gemm_top2,
                             cudaFuncAttributeMaxDynamicSharedMemorySize, SMEM_GEMM);
        smem_set = 1;
    }

    k_zero<<<(K_N * D_N + 255) / 256, 256>>>();
    k_transp<<<dim3(K_N / 32, D_N / 32), dim3(32, 8)>>>(embed);
    k_enorm<<<(K_N + 255) / 256, 256>>>(embed);
    k_gemm_top2<<<B_N / GBM, 512, SMEM_GEMM>>>(x, embed);
    k_assign<<<B_N / 8, 256>>>(x);
    k_fallback<<<1024, 256>>>(x, embed);
    k_quant<<<B_N / 8, 256>>>(x, out);
    k_stats<<<K_N / 256, 256>>>(cluster_size, out);
    k_final<<<(D_N * K_N + 255) / 256, 256>>>(embed_avg, out);
}

// round 8
// speedup vs baseline: 2.6977x; 1.1789x over previous
#include <cuda_runtime.h>
#include <cuda_fp16.h>
#include <cstdint>

// Problem constants
#define B_N 65536
#define D_N 256
#define K_N 4096
#define DECAYF 0.99f
#define OMDECAYF 0.01f
#define EPSF 1e-5f
#define TAU 0.25f

// Output layout (concatenated float32, tuple order)
#define OFF_IDX  0
#define OFF_Q    65536
#define OFF_NS   16842752
#define OFF_LOSS 16842753
#define OFF_CS   16842754
#define OFF_E    16846850

// ---------------- device scratch ----------------
__device__ float  g_sumT[K_N * D_N];     // [K,D] scatter-add of x
__device__ float  g_embedT[K_N * D_N];   // [K,D] fp32 codebook (exact rescore)
__device__ __half g_ebh[K_N * D_N];      // [K,D] fp16 codebook (GEMM B)
__device__ __half g_xh[B_N * D_N];       // [B,D] fp16 x (GEMM A)
__device__ float  g_counts[K_N];
__device__ float  g_enorm[K_N];
__device__ int    g_idx[B_N];
__device__ int    g_cand[B_N * 32];      // 32 candidates per row
__device__ int    g_fall[B_N];
__device__ int    g_nfall;
__device__ float  g_scalars[4];          // 0: loss_sum, 1: n_sum, 2: n_small

// ---------------- zero scratch -----------------
__global__ void k_zero() {
    int i = blockIdx.x * blockDim.x + threadIdx.x;
    if (i < K_N * D_N) g_sumT[i] = 0.0f;
    if (i < K_N) g_counts[i] = 0.0f;
    if (i < 4) g_scalars[i] = 0.0f;
    if (i == 0) g_nfall = 0;
}

// ---------------- transpose embed [D,K] -> [K,D] (f32 + fp16) --------------
__global__ void k_transp(const float* __restrict__ embed) {
    __shared__ float t[32][33];
    int bx = blockIdx.x, by = blockIdx.y;
    int kx = bx * 32 + threadIdx.x;
    int dy = by * 32 + threadIdx.y;
    #pragma unroll
    for (int i = 0; i < 32; i += 8)
        t[threadIdx.y + i][threadIdx.x] = embed[(dy + i) * K_N + kx];
    __syncthreads();
    int k2 = bx * 32 + threadIdx.y;
    int d2 = by * 32 + threadIdx.x;
    #pragma unroll
    for (int i = 0; i < 32; i += 8) {
        float v = t[threadIdx.x][threadIdx.y + i];
        g_embedT[(k2 + i) * D_N + d2] = v;
        g_ebh[(k2 + i) * D_N + d2] = __float2half_rn(v);
    }
}

// ---------------- x -> fp16 -------------------------------------------------
__global__ void k_tohalf(const float* __restrict__ x) {
    int i = blockIdx.x * blockDim.x + threadIdx.x;   // over B*D/4
    float4 v = reinterpret_cast<const float4*>(x)[i];
    __half2* o = reinterpret_cast<__half2*>(g_xh) + i * 2;
    o[0] = __floats2half2_rn(v.x, v.y);
    o[1] = __floats2half2_rn(v.z, v.w);
}

// ---------------- ||e_k||^2 (exact fp32) ----------------------------------
__global__ void k_enorm(const float* __restrict__ embed) {
    int k = blockIdx.x * blockDim.x + threadIdx.x;
    if (k >= K_N) return;
    float acc = 0.0f;
    #pragma unroll 8
    for (int d = 0; d < D_N; d++) {
        float v = embed[d * K_N + k];
        acc = fmaf(v, v, acc);
    }
    g_enorm[k] = acc;
}

// ---------------- mma + cp.async helpers -----------------------------------
__device__ __forceinline__ void mma_f16(float* c, const unsigned* a, const unsigned* b) {
    asm volatile(
        "mma.sync.aligned.m16n8k16.row.col.f32.f16.f16.f32 "
        "{%0,%1,%2,%3}, {%4,%5,%6,%7}, {%8,%9}, {%0,%1,%2,%3};\n"
        : "+f"(c[0]), "+f"(c[1]), "+f"(c[2]), "+f"(c[3])
        : "r"(a[0]), "r"(a[1]), "r"(a[2]), "r"(a[3]), "r"(b[0]), "r"(b[1]));
}
__device__ __forceinline__ void cp16(unsigned dst, const void* src) {
    asm volatile("cp.async.ca.shared.global [%0], [%1], 16;\n" :: "r"(dst), "l"(src));
}
__device__ __forceinline__ void cp_commit() { asm volatile("cp.async.commit_group;\n"); }
template <int N>
__device__ __forceinline__ void cp_wait() {
    asm volatile("cp.async.wait_group %0;\n" :: "n"(N));
}

// ---------------- fused fp16 GEMM (cp.async double-buffered) ---------------
// score(i,k) = ||e_k||^2 - 2 * x_i . e_k (fp16 ranking; exact rescore later)
#define GBM 256
#define GBN 128
#define GBK 32
#define AROW 40                 // GBK + 8 halfs pad; 80 bytes = 16B multiple
#define BROW 40
#define ABYTES (GBM * AROW * 2)
#define BBYTES (GBN * BROW * 2)
#define STAGE_BYTES (ABYTES + BBYTES)
#define SMEM_GEMM (2 * STAGE_BYTES)

__global__ __launch_bounds__(512, 1)
void k_gemm_top2(const __half* __restrict__ xh, const __half* __restrict__ ebh) {
    extern __shared__ __align__(16) unsigned char raw[];
    __shared__ float sEn[GBN];

    const int tid = threadIdx.x;
    const int m0 = blockIdx.x * GBM;
    const int warp = tid >> 5, lane = tid & 31;
    const int wm = warp >> 2, wn = warp & 3;   // 4x4 warp grid, warp tile 64x32
    const int g = lane >> 2, q = lane & 3;

    const unsigned smem_base = (unsigned)__cvta_generic_to_shared(raw);
    const __half* Af[2] = { reinterpret_cast<const __half*>(raw),
                            reinterpret_cast<const __half*>(raw + STAGE_BYTES) };
    const __half* Bf[2] = { reinterpret_cast<const __half*>(raw + ABYTES),
                            reinterpret_cast<const __half*>(raw + STAGE_BYTES + ABYTES) };

    float t1s[8], t2s[8];
    unsigned pk[8];
    #pragma unroll
    for (int i = 0; i < 8; i++) { t1s[i] = 3.4e38f; t2s[i] = 3.4e38f; pk[i] = 0; }

    const int NSTAGE = D_N / GBK;   // 8

    for (int n0 = 0; n0 < K_N; n0 += GBN) {
        float acc[4][4][4];
        #pragma unroll
        for (int a = 0; a < 4; a++)
            #pragma unroll
            for (int b = 0; b < 4; b++)
                #pragma unroll
                for (int c = 0; c < 4; c++) acc[a][b][c] = 0.0f;

        if (tid < GBN) sEn[tid] = g_enorm[n0 + tid];

        auto load_stage = [&](int buf, int d0) {
            unsigned abase = smem_base + buf * STAGE_BYTES;
            unsigned bbase = abase + ABYTES;
            // A: GBM rows x GBK halfs = 1024 16B chunks
            #pragma unroll
            for (int i = tid; i < GBM * GBK / 8; i += 512) {
                int r = i >> 2, c8 = i & 3;
                cp16(abase + r * (AROW * 2) + c8 * 16,
                     xh + (m0 + r) * D_N + d0 + c8 * 8);
            }
            // B: GBN rows (codes) x GBK halfs = 512 16B chunks
            #pragma unroll
            for (int i = tid; i < GBN * GBK / 8; i += 512) {
                int r = i >> 2, c8 = i & 3;
                cp16(bbase + r * (BROW * 2) + c8 * 16,
                     ebh + (n0 + r) * D_N + d0 + c8 * 8);
            }
            cp_commit();
        };

        load_stage(0, 0);
        for (int s = 0; s < NSTAGE; s++) {
            if (s + 1 < NSTAGE) {
                load_stage((s + 1) & 1, (s + 1) * GBK);
                cp_wait<1>();
            } else {
                cp_wait<0>();
            }
            __syncthreads();

            const __half* As = Af[s & 1];
            const __half* Bs = Bf[s & 1];
            #pragma unroll
            for (int k0 = 0; k0 < GBK; k0 += 16) {
                unsigned a[4][4], b[4][2];
                #pragma unroll
                for (int mf = 0; mf < 4; mf++) {
                    int mr = wm * 64 + mf * 16 + g;
                    const __half* p0 = As + mr * AROW + k0 + 2 * q;
                    const __half* p1 = As + (mr + 8) * AROW + k0 + 2 * q;
                    a[mf][0] = *reinterpret_cast<const unsigned*>(p0);
                    a[mf][1] = *reinterpret_cast<const unsigned*>(p1);
                    a[mf][2] = *reinterpret_cast<const unsigned*>(p0 + 8);
                    a[mf][3] = *reinterpret_cast<const unsigned*>(p1 + 8);
                }
                #pragma unroll
                for (int nf = 0; nf < 4; nf++) {
                    int nc = wn * 32 + nf * 8 + g;
                    const __half* p = Bs + nc * BROW + k0 + 2 * q;
                    b[nf][0] = *reinterpret_cast<const unsigned*>(p);
                    b[nf][1] = *reinterpret_cast<const unsigned*>(p + 8);
                }
                #pragma unroll
                for (int mf = 0; mf < 4; mf++)
                    #pragma unroll
                    for (int nf = 0; nf < 4; nf++)
                        mma_f16(acc[mf][nf], a[mf], b[nf]);
            }
            __syncthreads();
        }

        // fold scores into per-thread top-2
        #pragma unroll
        for (int nf = 0; nf < 4; nf++) {
            #pragma unroll
            for (int e = 0; e < 2; e++) {
                int col = wn * 32 + nf * 8 + 2 * q + e;
                float en = sEn[col];
                int k = n0 + col;
                #pragma unroll
                for (int mf = 0; mf < 4; mf++) {
                    #pragma unroll
                    for (int h = 0; h < 2; h++) {
                        float s = fmaf(-2.0f, acc[mf][nf][h * 2 + e], en);
                        int rid = mf * 2 + h;
                        if (s < t1s[rid]) {
                            t2s[rid] = t1s[rid];
                            t1s[rid] = s;
                            pk[rid] = ((pk[rid] & 0xffffu) << 16) | (unsigned)k;
                        } else if (s < t2s[rid]) {
                            t2s[rid] = s;
                            pk[rid] = (pk[rid] & 0xffffu) | ((unsigned)k << 16);
                        }
                    }
                }
            }
        }
    }

    const int slot = (wn * 4 + q) * 2;
    #pragma unroll
    for (int rid = 0; rid < 8; rid++) {
        int mf = rid >> 1, h = rid & 1;
        int row = m0 + wm * 64 + mf * 16 + h * 8 + g;
        g_cand[row * 32 + slot + 0] = (int)(pk[rid] & 0xffffu);
        g_cand[row * 32 + slot + 1] = (int)(pk[rid] >> 16);
    }
}

// ---------------- exact rescore (32 cands) + gap-certification -------------
__global__ __launch_bounds__(256)
void k_assign(const float* __restrict__ x) {
    int warp = threadIdx.x >> 5, lane = threadIdx.x & 31;
    int row = blockIdx.x * 8 + warp;
    const float4* xr = reinterpret_cast<const float4*>(x + row * D_N);
    float4 xa = xr[lane * 2], xb = xr[lane * 2 + 1];
    const int* cand = g_cand + row * 32;

    float bs = 3.4e38f, bs2 = 3.4e38f; int bk = 1 << 30;
    #pragma unroll 4
    for (int c = 0; c < 32; c++) {
        int k = cand[c];
        const float4* er = reinterpret_cast<const float4*>(g_embedT + k * D_N);
        float4 ea = er[lane * 2], eb = er[lane * 2 + 1];
        float dot = 0.0f;
        dot = fmaf(xa.x, ea.x, dot); dot = fmaf(xa.y, ea.y, dot);
        dot = fmaf(xa.z, ea.z, dot); dot = fmaf(xa.w, ea.w, dot);
        dot = fmaf(xb.x, eb.x, dot); dot = fmaf(xb.y, eb.y, dot);
        dot = fmaf(xb.z, eb.z, dot); dot = fmaf(xb.w, eb.w, dot);
        #pragma unroll
        for (int o = 16; o > 0; o >>= 1) dot += __shfl_xor_sync(0xffffffffu, dot, o);
        float s = fmaf(-2.0f, dot, g_enorm[k]);
        if (s < bs || (s == bs && k < bk)) { bs2 = bs; bs = s; bk = k; }
        else if (s < bs2) bs2 = s;
    }
    if (lane == 0) {
        g_idx[row] = bk;
        if (bs2 - bs < TAU) {
            int pos = atomicAdd(&g_nfall, 1);
            g_fall[pos] = row;
        }
    }
}

// ---------------- full exact scan for flagged rows -------------------------
__global__ __launch_bounds__(256)
void k_fallback(const float* __restrict__ x, const float* __restrict__ embed) {
    __shared__ float xs[D_N];
    __shared__ float rS[8];
    __shared__ int   rK[8];
    int tid = threadIdx.x, lane = tid & 31, warp = tid >> 5;
    int n = g_nfall;
    for (int w = blockIdx.x; w < n; w += gridDim.x) {
        int row = g_fall[w];
        __syncthreads();
        xs[tid] = x[row * D_N + tid];
        __syncthreads();

        float acc[16];
        #pragma unroll
        for (int j = 0; j < 16; j++) acc[j] = 0.0f;
        for (int d = 0; d < D_N; d++) {
            float xd = xs[d];
            const float* er = embed + d * K_N + tid;
            #pragma unroll
            for (int j = 0; j < 16; j++)
                acc[j] = fmaf(xd, er[j * 256], acc[j]);
        }
        float bs = 3.4e38f; int bk = 1 << 30;
        #pragma unroll
        for (int j = 0; j < 16; j++) {
            int k = tid + j * 256;
            float s = fmaf(-2.0f, acc[j], g_enorm[k]);
            if (s < bs || (s == bs && k < bk)) { bs = s; bk = k; }
        }
        #pragma unroll
        for (int o = 16; o > 0; o >>= 1) {
            float os = __shfl_down_sync(0xffffffffu, bs, o);
            int   ok = __shfl_down_sync(0xffffffffu, bk, o);
            if (os < bs || (os == bs && ok < bk)) { bs = os; bk = ok; }
        }
        if (lane == 0) { rS[warp] = bs; rK[warp] = bk; }
        __syncthreads();
        if (tid == 0) {
            float fbs = rS[0]; int fbk = rK[0];
            #pragma unroll
            for (int t = 1; t < 8; t++) {
                if (rS[t] < fbs || (rS[t] == fbs && rK[t] < fbk)) {
                    fbs = rS[t]; fbk = rK[t];
                }
            }
            g_idx[row] = fbk;
        }
    }
}

// ---------------- quantize + STE + loss + histogram + scatter-add ---------
__global__ __launch_bounds__(256)
void k_quant(const float* __restrict__ x, float* __restrict__ out) {
    __shared__ float blk_loss;
    if (threadIdx.x == 0) blk_loss = 0.0f;
    __syncthreads();

    int warp = threadIdx.x >> 5, lane = threadIdx.x & 31;
    int row = blockIdx.x * 8 + warp;
    int k = g_idx[row];
    const float4* xr = reinterpret_cast<const float4*>(x + row * D_N);
    const float4* er = reinterpret_cast<const float4*>(g_embedT + k * D_N);
    float4* outr = reinterpret_cast<float4*>(out + OFF_Q + row * D_N);
    float lacc = 0.0f;

    #pragma unroll
    for (int it = 0; it < 2; it++) {
        int c4 = lane * 2 + it;
        float4 xv = xr[c4];
        float4 ev = er[c4];
        float d0 = ev.x - xv.x, d1 = ev.y - xv.y, d2 = ev.z - xv.z, d3 = ev.w - xv.w;
        outr[c4] = make_float4(xv.x + d0, xv.y + d1, xv.z + d2, xv.w + d3);
        lacc = fmaf(d0, d0, lacc); lacc = fmaf(d1, d1, lacc);
        lacc = fmaf(d2, d2, lacc); lacc = fmaf(d3, d3, lacc);
        int d = c4 * 4;
        atomicAdd(&g_sumT[k * D_N + d + 0], xv.x);
        atomicAdd(&g_sumT[k * D_N + d + 1], xv.y);
        atomicAdd(&g_sumT[k * D_N + d + 2], xv.z);
        atomicAdd(&g_sumT[k * D_N + d + 3], xv.w);
    }
    #pragma unroll
    for (int o = 16; o > 0; o >>= 1) lacc += __shfl_down_sync(0xffffffffu, lacc, o);
    if (lane == 0) {
        atomicAdd(&blk_loss, lacc);
        atomicAdd(&g_counts[k], 1.0f);
        out[OFF_IDX + row] = (float)k;
    }
    __syncthreads();
    if (threadIdx.x == 0) atomicAdd(&g_scalars[0], blk_loss);
}

// ---------------- new_cluster_size + reductions ---------------------------
__global__ void k_stats(const float* __restrict__ cluster_size,
                        float* __restrict__ out) {
    __shared__ float sSum[256], sSmall[256];
    int tid = threadIdx.x;
    int k = blockIdx.x * 256 + tid;
    float ncs = fmaf(DECAYF, cluster_size[k], OMDECAYF * g_counts[k]);
    out[OFF_CS + k] = ncs;
    sSum[tid] = ncs;
    sSmall[tid] = (ncs < 1.0f) ? 1.0f : 0.0f;
    __syncthreads();
    for (int o = 128; o > 0; o >>= 1) {
        if (tid < o) { sSum[tid] += sSum[tid + o]; sSmall[tid] += sSmall[tid + o]; }
        __syncthreads();
    }
    if (tid == 0) {
        atomicAdd(&g_scalars[1], sSum[0]);
        atomicAdd(&g_scalars[2], sSmall[0]);
    }
}

// ---------------- finalize: new_embed + scalars ---------------------------
__global__ void k_final(const float* __restrict__ embed_avg,
                        float* __restrict__ out) {
    int i = blockIdx.x * blockDim.x + threadIdx.x;
    if (i == 0) {
        out[OFF_NS]   = g_scalars[2];
        out[OFF_LOSS] = g_scalars[0] * (1.0f / ((float)B_N * (float)D_N));
    }
    if (i < D_N * K_N) {
        int k = i & (K_N - 1);
        int d = i >> 12;
        float ncs = out[OFF_CS + k];
        float n = g_scalars[1];
        float cs = (ncs + EPSF) / (n + (float)K_N * EPSF) * n;
        float navg = fmaf(DECAYF, embed_avg[i], OMDECAYF * g_sumT[k * D_N + d]);
        out[OFF_E + i] = navg / cs;
    }
}

// ---------------- launch ---------------------------------------------------
extern "C" void kernel_launch(void* const* d_in, const int* in_sizes, int n_in,
                              void* d_out, int out_size) {
    const float* x            = (const float*)d_in[0];  // [B, D]
    const float* embed        = (const float*)d_in[1];  // [D, K]
    const float* cluster_size = (const float*)d_in[2];  // [K]
    const float* embed_avg    = (const float*)d_in[3];  // [D, K]
    float* out = (float*)d_out;
    (void)in_sizes; (void)n_in; (void)out_size;

    static int smem_set = 0;
    if (!smem_set) {
        cudaFuncSetAttribute(k_gemm_top2,
                             cudaFuncAttributeMaxDynamicSharedMemorySize, SMEM_GEMM);
        smem_set = 1;
    }

    __half* xh;  cudaGetSymbolAddress((void**)&xh, g_xh);
    __half* ebh; cudaGetSymbolAddress((void**)&ebh, g_ebh);

    k_zero<<<(K_N * D_N + 255) / 256, 256>>>();
    k_transp<<<dim3(K_N / 32, D_N / 32), dim3(32, 8)>>>(embed);
    k_tohalf<<<B_N * D_N / 4 / 256, 256>>>(x);
    k_enorm<<<(K_N + 255) / 256, 256>>>(embed);
    k_gemm_top2<<<B_N / GBM, 512, SMEM_GEMM>>>(xh, ebh);
    k_assign<<<B_N / 8, 256>>>(x);
    k_fallback<<<1024, 256>>>(x, embed);
    k_quant<<<B_N / 8, 256>>>(x, out);
    k_stats<<<K_N / 256, 256>>>(cluster_size, out);
    k_final<<<(D_N * K_N + 255) / 256, 256>>>(embed_avg, out);
}

// round 10
// speedup vs baseline: 3.0737x; 1.1393x over previous
#include <cuda_runtime.h>
#include <cuda_fp16.h>
#include <cstdint>

// Problem constants
#define B_N 65536
#define D_N 256
#define K_N 4096
#define DECAYF 0.99f
#define OMDECAYF 0.01f
#define EPSF 1e-5f
#define TAU 0.25f

// Output layout (concatenated float32, tuple order)
#define OFF_IDX  0
#define OFF_Q    65536
#define OFF_NS   16842752
#define OFF_LOSS 16842753
#define OFF_CS   16842754
#define OFF_E    16846850

// ---------------- device scratch ----------------
__device__ float  g_sumT[K_N * D_N];     // [K,D] scatter-add of x
__device__ float  g_embedT[K_N * D_N];   // [K,D] fp32 codebook (exact rescore)
__device__ __half g_ebh[K_N * D_N];      // [K,D] fp16 codebook (GEMM B)
__device__ __half g_xh[B_N * D_N];       // [B,D] fp16 x (GEMM A)
__device__ float  g_counts[K_N];
__device__ float  g_enorm[K_N];
__device__ int    g_idx[B_N];
__device__ int    g_cand[B_N * 32];      // 32 candidates per row
__device__ int    g_fall[B_N];
__device__ int    g_nfall;
__device__ float  g_scalars[4];          // 0: loss_sum, 1: n_sum, 2: n_small

// ---------------- zero scratch -----------------
__global__ void k_zero() {
    int i = blockIdx.x * blockDim.x + threadIdx.x;
    if (i < K_N * D_N) g_sumT[i] = 0.0f;
    if (i < K_N) g_counts[i] = 0.0f;
    if (i < 4) g_scalars[i] = 0.0f;
    if (i == 0) g_nfall = 0;
}

// ---------------- transpose embed [D,K] -> [K,D] (f32 + fp16) --------------
__global__ void k_transp(const float* __restrict__ embed) {
    __shared__ float t[32][33];
    int bx = blockIdx.x, by = blockIdx.y;
    int kx = bx * 32 + threadIdx.x;
    int dy = by * 32 + threadIdx.y;
    #pragma unroll
    for (int i = 0; i < 32; i += 8)
        t[threadIdx.y + i][threadIdx.x] = embed[(dy + i) * K_N + kx];
    __syncthreads();
    int k2 = bx * 32 + threadIdx.y;
    int d2 = by * 32 + threadIdx.x;
    #pragma unroll
    for (int i = 0; i < 32; i += 8) {
        float v = t[threadIdx.x][threadIdx.y + i];
        g_embedT[(k2 + i) * D_N + d2] = v;
        g_ebh[(k2 + i) * D_N + d2] = __float2half_rn(v);
    }
}

// ---------------- x -> fp16 -------------------------------------------------
__global__ void k_tohalf(const float* __restrict__ x) {
    int i = blockIdx.x * blockDim.x + threadIdx.x;   // over B*D/4
    float4 v = reinterpret_cast<const float4*>(x)[i];
    __half2* o = reinterpret_cast<__half2*>(g_xh) + i * 2;
    o[0] = __floats2half2_rn(v.x, v.y);
    o[1] = __floats2half2_rn(v.z, v.w);
}

// ---------------- ||e_k||^2 (exact fp32, reference accumulation order) -----
__global__ void k_enorm(const float* __restrict__ embed) {
    int k = blockIdx.x * blockDim.x + threadIdx.x;
    if (k >= K_N) return;
    float acc = 0.0f;
    #pragma unroll 8
    for (int d = 0; d < D_N; d++) {
        float v = embed[d * K_N + k];
        acc = fmaf(v, v, acc);
    }
    g_enorm[k] = acc;
}

// ---------------- mma / ldmatrix / cp.async helpers ------------------------
__device__ __forceinline__ void mma_f16(float* c, const unsigned* a, const unsigned* b) {
    asm volatile(
        "mma.sync.aligned.m16n8k16.row.col.f32.f16.f16.f32 "
        "{%0,%1,%2,%3}, {%4,%5,%6,%7}, {%8,%9}, {%0,%1,%2,%3};\n"
        : "+f"(c[0]), "+f"(c[1]), "+f"(c[2]), "+f"(c[3])
        : "r"(a[0]), "r"(a[1]), "r"(a[2]), "r"(a[3]), "r"(b[0]), "r"(b[1]));
}
#define LDSM_X4(r0, r1, r2, r3, addr) \
    asm volatile("ldmatrix.sync.aligned.m8n8.x4.shared.b16 {%0,%1,%2,%3}, [%4];" \
        : "=r"(r0), "=r"(r1), "=r"(r2), "=r"(r3) : "r"(addr))
__device__ __forceinline__ void cp16(unsigned dst, const void* src) {
    asm volatile("cp.async.ca.shared.global [%0], [%1], 16;\n" :: "r"(dst), "l"(src));
}
__device__ __forceinline__ void cp_commit() { asm volatile("cp.async.commit_group;\n"); }
template <int N>
__device__ __forceinline__ void cp_wait() {
    asm volatile("cp.async.wait_group %0;\n" :: "n"(N));
}

// ---------------- fused fp16 GEMM (ldmatrix + cp.async double-buffered) ----
// score(i,k) = ||e_k||^2 - 2 * x_i . e_k (fp16 ranking; exact rescore later)
#define GBM 256
#define GBN 128
#define GBK 64
#define AROWB 144               // (64 + 8 pad) halfs = 144 bytes per row
#define ABYTES (GBM * AROWB)    // 36864
#define BBYTES (GBN * AROWB)    // 18432
#define STAGE_BYTES (ABYTES + BBYTES)
#define SMEM_GEMM (2 * STAGE_BYTES)

__global__ __launch_bounds__(512, 1)
void k_gemm_top2(const __half* __restrict__ xh, const __half* __restrict__ ebh) {
    extern __shared__ __align__(16) unsigned char raw[];
    __shared__ float sEn[K_N];   // full enorm table, written ONCE (no race)

    const int tid = threadIdx.x;
    const int m0 = blockIdx.x * GBM;
    const int warp = tid >> 5, lane = tid & 31;
    const int wm = warp >> 2, wn = warp & 3;   // 4x4 warp grid, warp tile 64x32
    const int g = lane >> 2, q = lane & 3;

    const unsigned smem_base = (unsigned)__cvta_generic_to_shared(raw);

    for (int i = tid; i < K_N; i += 512) sEn[i] = g_enorm[i];

    // precomputed ldmatrix lane addresses (byte offsets within a stage buffer)
    // A: lanes 0-15 -> rows mr+0..15 at k0; lanes 16-31 -> same rows, +16B
    const unsigned a_lane_off = (unsigned)((lane & 15) * AROWB + ((lane >> 4) << 4));
    // B: lanes 0-7 rows nc+0..7 @k0; 8-15 same rows +16B; 16-23 rows nc+8..15 @k0; 24-31 +16B
    const unsigned b_lane_off =
        (unsigned)(((lane & 7) + ((lane & 16) >> 1)) * AROWB + ((lane & 8) << 1));

    float t1s[8], t2s[8];
    unsigned pk[8];
    #pragma unroll
    for (int i = 0; i < 8; i++) { t1s[i] = 3.4e38f; t2s[i] = 3.4e38f; pk[i] = 0; }

    const int NSTAGE = D_N / GBK;   // 4

    for (int n0 = 0; n0 < K_N; n0 += GBN) {
        float acc[4][4][4];
        #pragma unroll
        for (int a = 0; a < 4; a++)
            #pragma unroll
            for (int b = 0; b < 4; b++)
                #pragma unroll
                for (int c = 0; c < 4; c++) acc[a][b][c] = 0.0f;

        auto load_stage = [&](int buf, int d0) {
            unsigned abase = smem_base + buf * STAGE_BYTES;
            unsigned bbase = abase + ABYTES;
            // A: GBM rows x GBK halfs = 2048 16B chunks
            #pragma unroll
            for (int i = tid; i < GBM * GBK / 8; i += 512) {
                int r = i >> 3, c8 = i & 7;
                cp16(abase + r * AROWB + c8 * 16, xh + (m0 + r) * D_N + d0 + c8 * 8);
            }
            // B: GBN rows x GBK halfs = 1024 16B chunks
            #pragma unroll
            for (int i = tid; i < GBN * GBK / 8; i += 512) {
                int r = i >> 3, c8 = i & 7;
                cp16(bbase + r * AROWB + c8 * 16, ebh + (n0 + r) * D_N + d0 + c8 * 8);
            }
            cp_commit();
        };

        load_stage(0, 0);
        for (int s = 0; s < NSTAGE; s++) {
            if (s + 1 < NSTAGE) {
                load_stage((s + 1) & 1, (s + 1) * GBK);
                cp_wait<1>();
            } else {
                cp_wait<0>();
            }
            __syncthreads();

            const unsigned ab = smem_base + (s & 1) * STAGE_BYTES;
            const unsigned bb = ab + ABYTES;
            #pragma unroll
            for (int k0 = 0; k0 < GBK; k0 += 16) {
                unsigned a[4][4], b[2][4];
                #pragma unroll
                for (int mf = 0; mf < 4; mf++) {
                    unsigned addr = ab + (wm * 64 + mf * 16) * AROWB + a_lane_off + k0 * 2;
                    LDSM_X4(a[mf][0], a[mf][1], a[mf][2], a[mf][3], addr);
                }
                #pragma unroll
                for (int pr = 0; pr < 2; pr++) {
                    unsigned addr = bb + (wn * 32 + pr * 16) * AROWB + b_lane_off + k0 * 2;
                    LDSM_X4(b[pr][0], b[pr][1], b[pr][2], b[pr][3], addr);
                }
                #pragma unroll
                for (int mf = 0; mf < 4; mf++)
                    #pragma unroll
                    for (int nf = 0; nf < 4; nf++)
                        mma_f16(acc[mf][nf], a[mf], &b[nf >> 1][(nf & 1) * 2]);
            }
            __syncthreads();
        }

        // fold scores into per-thread top-2
        #pragma unroll
        for (int nf = 0; nf < 4; nf++) {
            #pragma unroll
            for (int e = 0; e < 2; e++) {
                int col = wn * 32 + nf * 8 + 2 * q + e;
                int k = n0 + col;
                float en = sEn[k];
                #pragma unroll
                for (int mf = 0; mf < 4; mf++) {
                    #pragma unroll
                    for (int h = 0; h < 2; h++) {
                        float s = fmaf(-2.0f, acc[mf][nf][h * 2 + e], en);
                        int rid = mf * 2 + h;
                        if (s < t1s[rid]) {
                            t2s[rid] = t1s[rid];
                            t1s[rid] = s;
                            pk[rid] = ((pk[rid] & 0xffffu) << 16) | (unsigned)k;
                        } else if (s < t2s[rid]) {
                            t2s[rid] = s;
                            pk[rid] = (pk[rid] & 0xffffu) | ((unsigned)k << 16);
                        }
                    }
                }
            }
        }
    }

    const int slot = (wn * 4 + q) * 2;
    #pragma unroll
    for (int rid = 0; rid < 8; rid++) {
        int mf = rid >> 1, h = rid & 1;
        int row = m0 + wm * 64 + mf * 16 + h * 8 + g;
        g_cand[row * 32 + slot + 0] = (int)(pk[rid] & 0xffffu);
        g_cand[row * 32 + slot + 1] = (int)(pk[rid] >> 16);
    }
}

// ---------------- exact rescore (32 cands) + gap-certification -------------
__global__ __launch_bounds__(256)
void k_assign(const float* __restrict__ x) {
    int warp = threadIdx.x >> 5, lane = threadIdx.x & 31;
    int row = blockIdx.x * 8 + warp;
    const float4* xr = reinterpret_cast<const float4*>(x + row * D_N);
    float4 xa = xr[lane * 2], xb = xr[lane * 2 + 1];
    const int* cand = g_cand + row * 32;

    float bs = 3.4e38f, bs2 = 3.4e38f; int bk = 1 << 30;
    #pragma unroll 4
    for (int c = 0; c < 32; c++) {
        int k = cand[c];
        const float4* er = reinterpret_cast<const float4*>(g_embedT + k * D_N);
        float4 ea = er[lane * 2], eb = er[lane * 2 + 1];
        float dot = 0.0f;
        dot = fmaf(xa.x, ea.x, dot); dot = fmaf(xa.y, ea.y, dot);
        dot = fmaf(xa.z, ea.z, dot); dot = fmaf(xa.w, ea.w, dot);
        dot = fmaf(xb.x, eb.x, dot); dot = fmaf(xb.y, eb.y, dot);
        dot = fmaf(xb.z, eb.z, dot); dot = fmaf(xb.w, eb.w, dot);
        #pragma unroll
        for (int o = 16; o > 0; o >>= 1) dot += __shfl_xor_sync(0xffffffffu, dot, o);
        float s = fmaf(-2.0f, dot, g_enorm[k]);
        if (s < bs || (s == bs && k < bk)) { bs2 = bs; bs = s; bk = k; }
        else if (s < bs2) bs2 = s;
    }
    if (lane == 0) {
        g_idx[row] = bk;
        if (bs2 - bs < TAU) {
            int pos = atomicAdd(&g_nfall, 1);
            g_fall[pos] = row;
        }
    }
}

// ---------------- full exact scan for flagged rows -------------------------
__global__ __launch_bounds__(256)
void k_fallback(const float* __restrict__ x, const float* __restrict__ embed) {
    __shared__ float xs[D_N];
    __shared__ float rS[8];
    __shared__ int   rK[8];
    int tid = threadIdx.x, lane = tid & 31, warp = tid >> 5;
    int n = g_nfall;
    for (int w = blockIdx.x; w < n; w += gridDim.x) {
        int row = g_fall[w];
        __syncthreads();
        xs[tid] = x[row * D_N + tid];
        __syncthreads();

        float acc[16];
        #pragma unroll
        for (int j = 0; j < 16; j++) acc[j] = 0.0f;
        for (int d = 0; d < D_N; d++) {
            float xd = xs[d];
            const float* er = embed + d * K_N + tid;
            #pragma unroll
            for (int j = 0; j < 16; j++)
                acc[j] = fmaf(xd, er[j * 256], acc[j]);
        }
        float bs = 3.4e38f; int bk = 1 << 30;
        #pragma unroll
        for (int j = 0; j < 16; j++) {
            int k = tid + j * 256;
            float s = fmaf(-2.0f, acc[j], g_enorm[k]);
            if (s < bs || (s == bs && k < bk)) { bs = s; bk = k; }
        }
        #pragma unroll
        for (int o = 16; o > 0; o >>= 1) {
            float os = __shfl_down_sync(0xffffffffu, bs, o);
            int   ok = __shfl_down_sync(0xffffffffu, bk, o);
            if (os < bs || (os == bs && ok < bk)) { bs = os; bk = ok; }
        }
        if (lane == 0) { rS[warp] = bs; rK[warp] = bk; }
        __syncthreads();
        if (tid == 0) {
            float fbs = rS[0]; int fbk = rK[0];
            #pragma unroll
            for (int t = 1; t < 8; t++) {
                if (rS[t] < fbs || (rS[t] == fbs && rK[t] < fbk)) {
                    fbs = rS[t]; fbk = rK[t];
                }
            }
            g_idx[row] = fbk;
        }
    }
}

// ---------------- quantize + STE + loss + histogram + scatter-add ---------
__global__ __launch_bounds__(256)
void k_quant(const float* __restrict__ x, float* __restrict__ out) {
    __shared__ float blk_loss;
    if (threadIdx.x == 0) blk_loss = 0.0f;
    __syncthreads();

    int warp = threadIdx.x >> 5, lane = threadIdx.x & 31;
    int row = blockIdx.x * 8 + warp;
    int k = g_idx[row];
    const float4* xr = reinterpret_cast<const float4*>(x + row * D_N);
    const float4* er = reinterpret_cast<const float4*>(g_embedT + k * D_N);
    float4* outr = reinterpret_cast<float4*>(out + OFF_Q + row * D_N);
    float lacc = 0.0f;

    #pragma unroll
    for (int it = 0; it < 2; it++) {
        int c4 = lane * 2 + it;
        float4 xv = xr[c4];
        float4 ev = er[c4];
        float d0 = ev.x - xv.x, d1 = ev.y - xv.y, d2 = ev.z - xv.z, d3 = ev.w - xv.w;
        outr[c4] = make_float4(xv.x + d0, xv.y + d1, xv.z + d2, xv.w + d3);
        lacc = fmaf(d0, d0, lacc); lacc = fmaf(d1, d1, lacc);
        lacc = fmaf(d2, d2, lacc); lacc = fmaf(d3, d3, lacc);
        int d = c4 * 4;
        atomicAdd(&g_sumT[k * D_N + d + 0], xv.x);
        atomicAdd(&g_sumT[k * D_N + d + 1], xv.y);
        atomicAdd(&g_sumT[k * D_N + d + 2], xv.z);
        atomicAdd(&g_sumT[k * D_N + d + 3], xv.w);
    }
    #pragma unroll
    for (int o = 16; o > 0; o >>= 1) lacc += __shfl_down_sync(0xffffffffu, lacc, o);
    if (lane == 0) {
        atomicAdd(&blk_loss, lacc);
        atomicAdd(&g_counts[k], 1.0f);
        out[OFF_IDX + row] = (float)k;
    }
    __syncthreads();
    if (threadIdx.x == 0) atomicAdd(&g_scalars[0], blk_loss);
}

// ---------------- new_cluster_size + reductions ---------------------------
__global__ void k_stats(const float* __restrict__ cluster_size,
                        float* __restrict__ out) {
    __shared__ float sSum[256], sSmall[256];
    int tid = threadIdx.x;
    int k = blockIdx.x * 256 + tid;
    float ncs = fmaf(DECAYF, cluster_size[k], OMDECAYF * g_counts[k]);
    out[OFF_CS + k] = ncs;
    sSum[tid] = ncs;
    sSmall[tid] = (ncs < 1.0f) ? 1.0f : 0.0f;
    __syncthreads();
    for (int o = 128; o > 0; o >>= 1) {
        if (tid < o) { sSum[tid] += sSum[tid + o]; sSmall[tid] += sSmall[tid + o]; }
        __syncthreads();
    }
    if (tid == 0) {
        atomicAdd(&g_scalars[1], sSum[0]);
        atomicAdd(&g_scalars[2], sSmall[0]);
    }
}

// ---------------- finalize: new_embed + scalars ---------------------------
__global__ void k_final(const float* __restrict__ embed_avg,
                        float* __restrict__ out) {
    int i = blockIdx.x * blockDim.x + threadIdx.x;
    if (i == 0) {
        out[OFF_NS]   = g_scalars[2];
        out[OFF_LOSS] = g_scalars[0] * (1.0f / ((float)B_N * (float)D_N));
    }
    if (i < D_N * K_N) {
        int k = i & (K_N - 1);
        int d = i >> 12;
        float ncs = out[OFF_CS + k];
        float n = g_scalars[1];
        float cs = (ncs + EPSF) / (n + (float)K_N * EPSF) * n;
        float navg = fmaf(DECAYF, embed_avg[i], OMDECAYF * g_sumT[k * D_N + d]);
        out[OFF_E + i] = navg / cs;
    }
}

// ---------------- launch ---------------------------------------------------
extern "C" void kernel_launch(void* const* d_in, const int* in_sizes, int n_in,
                              void* d_out, int out_size) {
    const float* x            = (const float*)d_in[0];  // [B, D]
    const float* embed        = (const float*)d_in[1];  // [D, K]
    const float* cluster_size = (const float*)d_in[2];  // [K]
    const float* embed_avg    = (const float*)d_in[3];  // [D, K]
    float* out = (float*)d_out;
    (void)in_sizes; (void)n_in; (void)out_size;

    static int smem_set = 0;
    if (!smem_set) {
        cudaFuncSetAttribute(k_gemm_top2,
                             cudaFuncAttributeMaxDynamicSharedMemorySize, SMEM_GEMM);
        smem_set = 1;
    }

    __half* xh;  cudaGetSymbolAddress((void**)&xh, g_xh);
    __half* ebh; cudaGetSymbolAddress((void**)&ebh, g_ebh);

    k_zero<<<(K_N * D_N + 255) / 256, 256>>>();
    k_transp<<<dim3(K_N / 32, D_N / 32), dim3(32, 8)>>>(embed);
    k_tohalf<<<B_N * D_N / 4 / 256, 256>>>(x);
    k_enorm<<<(K_N + 255) / 256, 256>>>(embed);
    k_gemm_top2<<<B_N / GBM, 512, SMEM_GEMM>>>(xh, ebh);
    k_assign<<<B_N / 8, 256>>>(x);
    k_fallback<<<1024, 256>>>(x, embed);
    k_quant<<<B_N / 8, 256>>>(x, out);
    k_stats<<<K_N / 256, 256>>>(cluster_size, out);
    k_final<<<(D_N * K_N + 255) / 256, 256>>>(embed_avg, out);
}

// round 12
// speedup vs baseline: 3.0850x; 1.0037x over previous
#include <cuda_runtime.h>
#include <cuda_fp16.h>
#include <cstdint>

// Problem constants
#define B_N 65536
#define D_N 256
#define K_N 4096
#define DECAYF 0.99f
#define OMDECAYF 0.01f
#define EPSF 1e-5f
#define TAU 0.25f

// Output layout (concatenated float32, tuple order)
#define OFF_IDX  0
#define OFF_Q    65536
#define OFF_NS   16842752
#define OFF_LOSS 16842753
#define OFF_CS   16842754
#define OFF_E    16846850

// ---------------- device scratch ----------------
__device__ float  g_sumT[K_N * D_N];     // [K,D] scatter-add of x
__device__ float  g_embedT[K_N * D_N];   // [K,D] fp32 codebook (exact rescore)
__device__ __half g_ebh[K_N * D_N];      // [K,D] fp16 codebook (GEMM B)
__device__ __half g_xh[B_N * D_N];       // [B,D] fp16 x (GEMM A)
__device__ float  g_counts[K_N];
__device__ float  g_enorm[K_N];
__device__ int    g_idx[B_N];
__device__ int    g_cand[B_N * 32];      // 32 candidates per row
__device__ int    g_fall[B_N];
__device__ int    g_nfall;
__device__ float  g_scalars[4];          // 0: loss_sum, 1: n_sum, 2: n_small

// ---------------- zero scratch -----------------
__global__ void k_zero() {
    int i = blockIdx.x * blockDim.x + threadIdx.x;
    if (i < K_N * D_N) g_sumT[i] = 0.0f;
    if (i < K_N) g_counts[i] = 0.0f;
    if (i < 4) g_scalars[i] = 0.0f;
    if (i == 0) g_nfall = 0;
}

// ---------------- transpose embed [D,K] -> [K,D] (f32 + fp16) --------------
__global__ void k_transp(const float* __restrict__ embed) {
    __shared__ float t[32][33];
    int bx = blockIdx.x, by = blockIdx.y;
    int kx = bx * 32 + threadIdx.x;
    int dy = by * 32 + threadIdx.y;
    #pragma unroll
    for (int i = 0; i < 32; i += 8)
        t[threadIdx.y + i][threadIdx.x] = embed[(dy + i) * K_N + kx];
    __syncthreads();
    int k2 = bx * 32 + threadIdx.y;
    int d2 = by * 32 + threadIdx.x;
    #pragma unroll
    for (int i = 0; i < 32; i += 8) {
        float v = t[threadIdx.x][threadIdx.y + i];
        g_embedT[(k2 + i) * D_N + d2] = v;
        g_ebh[(k2 + i) * D_N + d2] = __float2half_rn(v);
    }
}

// ---------------- x -> fp16 -------------------------------------------------
__global__ void k_tohalf(const float* __restrict__ x) {
    int i = blockIdx.x * blockDim.x + threadIdx.x;   // over B*D/4
    float4 v = reinterpret_cast<const float4*>(x)[i];
    __half2* o = reinterpret_cast<__half2*>(g_xh) + i * 2;
    o[0] = __floats2half2_rn(v.x, v.y);
    o[1] = __floats2half2_rn(v.z, v.w);
}

// ---------------- ||e_k||^2 (exact fp32) -----------------------------------
__global__ void k_enorm(const float* __restrict__ embed) {
    int k = blockIdx.x * blockDim.x + threadIdx.x;
    if (k >= K_N) return;
    float acc = 0.0f;
    #pragma unroll 8
    for (int d = 0; d < D_N; d++) {
        float v = embed[d * K_N + k];
        acc = fmaf(v, v, acc);
    }
    g_enorm[k] = acc;
}

// ---------------- mma / ldmatrix / cp.async helpers ------------------------
__device__ __forceinline__ void mma_f16(float* c, const unsigned* a, const unsigned* b) {
    asm volatile(
        "mma.sync.aligned.m16n8k16.row.col.f32.f16.f16.f32 "
        "{%0,%1,%2,%3}, {%4,%5,%6,%7}, {%8,%9}, {%0,%1,%2,%3};\n"
        : "+f"(c[0]), "+f"(c[1]), "+f"(c[2]), "+f"(c[3])
        : "r"(a[0]), "r"(a[1]), "r"(a[2]), "r"(a[3]), "r"(b[0]), "r"(b[1]));
}
#define LDSM_X4(r0, r1, r2, r3, addr) \
    asm volatile("ldmatrix.sync.aligned.m8n8.x4.shared.b16 {%0,%1,%2,%3}, [%4];" \
        : "=r"(r0), "=r"(r1), "=r"(r2), "=r"(r3) : "r"(addr))
__device__ __forceinline__ void cp16(unsigned dst, const void* src) {
    asm volatile("cp.async.ca.shared.global [%0], [%1], 16;\n" :: "r"(dst), "l"(src));
}
__device__ __forceinline__ void cp_commit() { asm volatile("cp.async.commit_group;\n"); }
template <int N>
__device__ __forceinline__ void cp_wait() {
    asm volatile("cp.async.wait_group %0;\n" :: "n"(N));
}

// ---------------- fused fp16 GEMM: A resident, B double-buffered ----------
// score(i,k) = ||e_k||^2 - 2 * x_i . e_k (fp16 ranking; exact rescore later)
#define GBM 128
#define GBN 128
#define AROWB 528               // (256 + 8 pad) halfs = 528 bytes per row
#define ABYTES (GBM * AROWB)    // 67584
#define BBYTES (GBN * AROWB)    // 67584
#define SMEM_GEMM (ABYTES + 2 * BBYTES)   // 202752
#define NT (K_N / GBN)          // 32

__global__ __launch_bounds__(512, 1)
void k_gemm_top2(const __half* __restrict__ xh, const __half* __restrict__ ebh) {
    extern __shared__ __align__(16) unsigned char raw[];
    __shared__ float sEn[K_N];   // full enorm table, written once

    const int tid = threadIdx.x;
    const int m0 = blockIdx.x * GBM;
    const int warp = tid >> 5, lane = tid & 31;
    const int wm = warp >> 2, wn = warp & 3;   // 4x4 warp grid, warp tile 32x32
    const int g = lane >> 2, q = lane & 3;

    const unsigned sA = (unsigned)__cvta_generic_to_shared(raw);
    const unsigned sB0 = sA + ABYTES;

    for (int i = tid; i < K_N; i += 512) sEn[i] = g_enorm[i];

    // ldmatrix lane offsets
    const unsigned a_lane_off = (unsigned)((lane & 15) * AROWB + ((lane >> 4) << 4));
    const unsigned b_lane_off =
        (unsigned)(((lane & 7) + ((lane & 16) >> 1)) * AROWB + ((lane & 8) << 1));

    // ---- load A (whole 128 x 256 tile) once ----
    #pragma unroll
    for (int i = tid; i < GBM * 32; i += 512) {          // 32 16B chunks per row
        int r = i >> 5, c8 = i & 31;
        cp16(sA + r * AROWB + c8 * 16, xh + (m0 + r) * D_N + c8 * 8);
    }
    cp_commit();
    // ---- load B tile 0 ----
    #pragma unroll
    for (int i = tid; i < GBN * 32; i += 512) {
        int r = i >> 5, c8 = i & 31;
        cp16(sB0 + r * AROWB + c8 * 16, ebh + r * D_N + c8 * 8);
    }
    cp_commit();

    float t1s[4], t2s[4];
    unsigned pk[4];
    #pragma unroll
    for (int i = 0; i < 4; i++) { t1s[i] = 3.4e38f; t2s[i] = 3.4e38f; pk[i] = 0; }

    for (int t = 0; t < NT; t++) {
        const unsigned bb = sB0 + (t & 1) * BBYTES;
        // prefetch next B tile into the other buffer
        if (t + 1 < NT) {
            const __half* src = ebh + (t + 1) * GBN * D_N;
            unsigned nb = sB0 + ((t + 1) & 1) * BBYTES;
            #pragma unroll
            for (int i = tid; i < GBN * 32; i += 512) {
                int r = i >> 5, c8 = i & 31;
                cp16(nb + r * AROWB + c8 * 16, src + r * D_N + c8 * 8);
            }
            cp_commit();
            cp_wait<1>();
        } else {
            cp_wait<0>();
        }
        __syncthreads();

        float acc[2][4][4];
        #pragma unroll
        for (int a = 0; a < 2; a++)
            #pragma unroll
            for (int b = 0; b < 4; b++)
                #pragma unroll
                for (int c = 0; c < 4; c++) acc[a][b][c] = 0.0f;

        // full-K inner loop: no barriers, 16 unrolled steps
        #pragma unroll
        for (int k0 = 0; k0 < D_N; k0 += 16) {
            unsigned a[2][4], b[2][4];
            #pragma unroll
            for (int mf = 0; mf < 2; mf++) {
                unsigned addr = sA + (wm * 32 + mf * 16) * AROWB + a_lane_off + k0 * 2;
                LDSM_X4(a[mf][0], a[mf][1], a[mf][2], a[mf][3], addr);
            }
            #pragma unroll
            for (int pr = 0; pr < 2; pr++) {
                unsigned addr = bb + (wn * 32 + pr * 16) * AROWB + b_lane_off + k0 * 2;
                LDSM_X4(b[pr][0], b[pr][1], b[pr][2], b[pr][3], addr);
            }
            #pragma unroll
            for (int mf = 0; mf < 2; mf++)
                #pragma unroll
                for (int nf = 0; nf < 4; nf++)
                    mma_f16(acc[mf][nf], a[mf], &b[nf >> 1][(nf & 1) * 2]);
        }
        __syncthreads();   // done reading B[t&1] before its reload at t+2

        // fold scores into per-thread top-2
        const int n0 = t * GBN;
        #pragma unroll
        for (int nf = 0; nf < 4; nf++) {
            #pragma unroll
            for (int e = 0; e < 2; e++) {
                int col = wn * 32 + nf * 8 + 2 * q + e;
                int k = n0 + col;
                float en = sEn[k];
                #pragma unroll
                for (int mf = 0; mf < 2; mf++) {
                    #pragma unroll
                    for (int h = 0; h < 2; h++) {
                        float s = fmaf(-2.0f, acc[mf][nf][h * 2 + e], en);
                        int rid = mf * 2 + h;
                        if (s < t1s[rid]) {
                            t2s[rid] = t1s[rid];
                            t1s[rid] = s;
                            pk[rid] = ((pk[rid] & 0xffffu) << 16) | (unsigned)k;
                        } else if (s < t2s[rid]) {
                            t2s[rid] = s;
                            pk[rid] = (pk[rid] & 0xffffu) | ((unsigned)k << 16);
                        }
                    }
                }
            }
        }
    }

    const int slot = (wn * 4 + q) * 2;
    #pragma unroll
    for (int rid = 0; rid < 4; rid++) {
        int mf = rid >> 1, h = rid & 1;
        int row = m0 + wm * 32 + mf * 16 + h * 8 + g;
        g_cand[row * 32 + slot + 0] = (int)(pk[rid] & 0xffffu);
        g_cand[row * 32 + slot + 1] = (int)(pk[rid] >> 16);
    }
}

// ---------------- exact rescore (32 cands) + gap-certification -------------
__global__ __launch_bounds__(256)
void k_assign(const float* __restrict__ x) {
    int warp = threadIdx.x >> 5, lane = threadIdx.x & 31;
    int row = blockIdx.x * 8 + warp;
    const float4* xr = reinterpret_cast<const float4*>(x + row * D_N);
    float4 xa = xr[lane * 2], xb = xr[lane * 2 + 1];
    const int* cand = g_cand + row * 32;

    float bs = 3.4e38f, bs2 = 3.4e38f; int bk = 1 << 30;
    #pragma unroll 4
    for (int c = 0; c < 32; c++) {
        int k = cand[c];
        const float4* er = reinterpret_cast<const float4*>(g_embedT + k * D_N);
        float4 ea = er[lane * 2], eb = er[lane * 2 + 1];
        float dot = 0.0f;
        dot = fmaf(xa.x, ea.x, dot); dot = fmaf(xa.y, ea.y, dot);
        dot = fmaf(xa.z, ea.z, dot); dot = fmaf(xa.w, ea.w, dot);
        dot = fmaf(xb.x, eb.x, dot); dot = fmaf(xb.y, eb.y, dot);
        dot = fmaf(xb.z, eb.z, dot); dot = fmaf(xb.w, eb.w, dot);
        #pragma unroll
        for (int o = 16; o > 0; o >>= 1) dot += __shfl_xor_sync(0xffffffffu, dot, o);
        float s = fmaf(-2.0f, dot, g_enorm[k]);
        if (s < bs || (s == bs && k < bk)) { bs2 = bs; bs = s; bk = k; }
        else if (s < bs2) bs2 = s;
    }
    if (lane == 0) {
        g_idx[row] = bk;
        if (bs2 - bs < TAU) {
            int pos = atomicAdd(&g_nfall, 1);
            g_fall[pos] = row;
        }
    }
}

// ---------------- full exact scan for flagged rows -------------------------
__global__ __launch_bounds__(256)
void k_fallback(const float* __restrict__ x, const float* __restrict__ embed) {
    __shared__ float xs[D_N];
    __shared__ float rS[8];
    __shared__ int   rK[8];
    int tid = threadIdx.x, lane = tid & 31, warp = tid >> 5;
    int n = g_nfall;
    for (int w = blockIdx.x; w < n; w += gridDim.x) {
        int row = g_fall[w];
        __syncthreads();
        xs[tid] = x[row * D_N + tid];
        __syncthreads();

        float acc[16];
        #pragma unroll
        for (int j = 0; j < 16; j++) acc[j] = 0.0f;
        for (int d = 0; d < D_N; d++) {
            float xd = xs[d];
            const float* er = embed + d * K_N + tid;
            #pragma unroll
            for (int j = 0; j < 16; j++)
                acc[j] = fmaf(xd, er[j * 256], acc[j]);
        }
        float bs = 3.4e38f; int bk = 1 << 30;
        #pragma unroll
        for (int j = 0; j < 16; j++) {
            int k = tid + j * 256;
            float s = fmaf(-2.0f, acc[j], g_enorm[k]);
            if (s < bs || (s == bs && k < bk)) { bs = s; bk = k; }
        }
        #pragma unroll
        for (int o = 16; o > 0; o >>= 1) {
            float os = __shfl_down_sync(0xffffffffu, bs, o);
            int   ok = __shfl_down_sync(0xffffffffu, bk, o);
            if (os < bs || (os == bs && ok < bk)) { bs = os; bk = ok; }
        }
        if (lane == 0) { rS[warp] = bs; rK[warp] = bk; }
        __syncthreads();
        if (tid == 0) {
            float fbs = rS[0]; int fbk = rK[0];
            #pragma unroll
            for (int t = 1; t < 8; t++) {
                if (rS[t] < fbs || (rS[t] == fbs && rK[t] < fbk)) {
                    fbs = rS[t]; fbk = rK[t];
                }
            }
            g_idx[row] = fbk;
        }
    }
}

// ---------------- quantize + STE + loss + histogram + scatter-add ---------
__global__ __launch_bounds__(256)
void k_quant(const float* __restrict__ x, float* __restrict__ out) {
    __shared__ float blk_loss;
    if (threadIdx.x == 0) blk_loss = 0.0f;
    __syncthreads();

    int warp = threadIdx.x >> 5, lane = threadIdx.x & 31;
    int row = blockIdx.x * 8 + warp;
    int k = g_idx[row];
    const float4* xr = reinterpret_cast<const float4*>(x + row * D_N);
    const float4* er = reinterpret_cast<const float4*>(g_embedT + k * D_N);
    float4* outr = reinterpret_cast<float4*>(out + OFF_Q + row * D_N);
    float lacc = 0.0f;

    #pragma unroll
    for (int it = 0; it < 2; it++) {
        int c4 = lane * 2 + it;
        float4 xv = xr[c4];
        float4 ev = er[c4];
        float d0 = ev.x - xv.x, d1 = ev.y - xv.y, d2 = ev.z - xv.z, d3 = ev.w - xv.w;
        outr[c4] = make_float4(xv.x + d0, xv.y + d1, xv.z + d2, xv.w + d3);
        lacc = fmaf(d0, d0, lacc); lacc = fmaf(d1, d1, lacc);
        lacc = fmaf(d2, d2, lacc); lacc = fmaf(d3, d3, lacc);
        int d = c4 * 4;
        atomicAdd(&g_sumT[k * D_N + d + 0], xv.x);
        atomicAdd(&g_sumT[k * D_N + d + 1], xv.y);
        atomicAdd(&g_sumT[k * D_N + d + 2], xv.z);
        atomicAdd(&g_sumT[k * D_N + d + 3], xv.w);
    }
    #pragma unroll
    for (int o = 16; o > 0; o >>= 1) lacc += __shfl_down_sync(0xffffffffu, lacc, o);
    if (lane == 0) {
        atomicAdd(&blk_loss, lacc);
        atomicAdd(&g_counts[k], 1.0f);
        out[OFF_IDX + row] = (float)k;
    }
    __syncthreads();
    if (threadIdx.x == 0) atomicAdd(&g_scalars[0], blk_loss);
}

// ---------------- new_cluster_size + reductions ---------------------------
__global__ void k_stats(const float* __restrict__ cluster_size,
                        float* __restrict__ out) {
    __shared__ float sSum[256], sSmall[256];
    int tid = threadIdx.x;
    int k = blockIdx.x * 256 + tid;
    float ncs = fmaf(DECAYF, cluster_size[k], OMDECAYF * g_counts[k]);
    out[OFF_CS + k] = ncs;
    sSum[tid] = ncs;
    sSmall[tid] = (ncs < 1.0f) ? 1.0f : 0.0f;
    __syncthreads();
    for (int o = 128; o > 0; o >>= 1) {
        if (tid < o) { sSum[tid] += sSum[tid + o]; sSmall[tid] += sSmall[tid + o]; }
        __syncthreads();
    }
    if (tid == 0) {
        atomicAdd(&g_scalars[1], sSum[0]);
        atomicAdd(&g_scalars[2], sSmall[0]);
    }
}

// ---------------- finalize: new_embed + scalars ---------------------------
__global__ void k_final(const float* __restrict__ embed_avg,
                        float* __restrict__ out) {
    int i = blockIdx.x * blockDim.x + threadIdx.x;
    if (i == 0) {
        out[OFF_NS]   = g_scalars[2];
        out[OFF_LOSS] = g_scalars[0] * (1.0f / ((float)B_N * (float)D_N));
    }
    if (i < D_N * K_N) {
        int k = i & (K_N - 1);
        int d = i >> 12;
        float ncs = out[OFF_CS + k];
        float n = g_scalars[1];
        float cs = (ncs + EPSF) / (n + (float)K_N * EPSF) * n;
        float navg = fmaf(DECAYF, embed_avg[i], OMDECAYF * g_sumT[k * D_N + d]);
        out[OFF_E + i] = navg / cs;
    }
}

// ---------------- launch ---------------------------------------------------
extern "C" void kernel_launch(void* const* d_in, const int* in_sizes, int n_in,
                              void* d_out, int out_size) {
    const float* x            = (const float*)d_in[0];  // [B, D]
    const float* embed        = (const float*)d_in[1];  // [D, K]
    const float* cluster_size = (const float*)d_in[2];  // [K]
    const float* embed_avg    = (const float*)d_in[3];  // [D, K]
    float* out = (float*)d_out;
    (void)in_sizes; (void)n_in; (void)out_size;

    static int smem_set = 0;
    if (!smem_set) {
        cudaFuncSetAttribute(k_gemm_top2,
                             cudaFuncAttributeMaxDynamicSharedMemorySize, SMEM_GEMM);
        smem_set = 1;
    }

    __half* xh;  cudaGetSymbolAddress((void**)&xh, g_xh);
    __half* ebh; cudaGetSymbolAddress((void**)&ebh, g_ebh);

    k_zero<<<(K_N * D_N + 255) / 256, 256>>>();
    k_transp<<<dim3(K_N / 32, D_N / 32), dim3(32, 8)>>>(embed);
    k_tohalf<<<B_N * D_N / 4 / 256, 256>>>(x);
    k_enorm<<<(K_N + 255) / 256, 256>>>(embed);
    k_gemm_top2<<<B_N / GBM, 512, SMEM_GEMM>>>(xh, ebh);
    k_assign<<<B_N / 8, 256>>>(x);
    k_fallback<<<1024, 256>>>(x, embed);
    k_quant<<<B_N / 8, 256>>>(x, out);
    k_stats<<<K_N / 256, 256>>>(cluster_size, out);
    k_final<<<(D_N * K_N + 255) / 256, 256>>>(embed_avg, out);
}

// round 13
// speedup vs baseline: 3.8096x; 1.2349x over previous
#include <cuda_runtime.h>
#include <cuda_fp16.h>
#include <cstdint>

// Problem constants
#define B_N 65536
#define D_N 256
#define K_N 4096
#define DECAYF 0.99f
#define OMDECAYF 0.01f
#define EPSF 1e-5f
#define TAU 0.25f

// Output layout (concatenated float32, tuple order)
#define OFF_IDX  0
#define OFF_Q    65536
#define OFF_NS   16842752
#define OFF_LOSS 16842753
#define OFF_CS   16842754
#define OFF_E    16846850

// ---------------- device scratch ----------------
__device__ float  g_sumT[K_N * D_N];     // [K,D] scatter-add of x
__device__ float  g_embedT[K_N * D_N];   // [K,D] fp32 codebook
__device__ __half g_ebh[K_N * D_N];      // [K,D] fp16 codebook (GEMM B)
__device__ __half g_xh[B_N * D_N];       // [B,D] fp16 x (GEMM A)
__device__ float  g_counts[K_N];
__device__ float  g_enorm[K_N];
__device__ int    g_idx[B_N];
__device__ int    g_fall[B_N];
__device__ int    g_nfall;
__device__ float  g_scalars[4];          // 0: loss_sum, 1: n_sum, 2: n_small

// ---------------- zero scratch -----------------
__global__ void k_zero() {
    int i = blockIdx.x * blockDim.x + threadIdx.x;
    if (i < K_N * D_N) g_sumT[i] = 0.0f;
    if (i < K_N) g_counts[i] = 0.0f;
    if (i < 4) g_scalars[i] = 0.0f;
    if (i == 0) g_nfall = 0;
}

// ---------------- transpose embed [D,K] -> [K,D] (f32 + fp16) --------------
__global__ void k_transp(const float* __restrict__ embed) {
    __shared__ float t[32][33];
    int bx = blockIdx.x, by = blockIdx.y;
    int kx = bx * 32 + threadIdx.x;
    int dy = by * 32 + threadIdx.y;
    #pragma unroll
    for (int i = 0; i < 32; i += 8)
        t[threadIdx.y + i][threadIdx.x] = embed[(dy + i) * K_N + kx];
    __syncthreads();
    int k2 = bx * 32 + threadIdx.y;
    int d2 = by * 32 + threadIdx.x;
    #pragma unroll
    for (int i = 0; i < 32; i += 8) {
        float v = t[threadIdx.x][threadIdx.y + i];
        g_embedT[(k2 + i) * D_N + d2] = v;
        g_ebh[(k2 + i) * D_N + d2] = __float2half_rn(v);
    }
}

// ---------------- x -> fp16 -------------------------------------------------
__global__ void k_tohalf(const float* __restrict__ x) {
    int i = blockIdx.x * blockDim.x + threadIdx.x;   // over B*D/4
    float4 v = reinterpret_cast<const float4*>(x)[i];
    __half2* o = reinterpret_cast<__half2*>(g_xh) + i * 2;
    o[0] = __floats2half2_rn(v.x, v.y);
    o[1] = __floats2half2_rn(v.z, v.w);
}

// ---------------- ||e_k||^2 (exact fp32) -----------------------------------
__global__ void k_enorm(const float* __restrict__ embed) {
    int k = blockIdx.x * blockDim.x + threadIdx.x;
    if (k >= K_N) return;
    float acc = 0.0f;
    #pragma unroll 8
    for (int d = 0; d < D_N; d++) {
        float v = embed[d * K_N + k];
        acc = fmaf(v, v, acc);
    }
    g_enorm[k] = acc;
}

// ---------------- mma / ldmatrix / cp.async helpers ------------------------
__device__ __forceinline__ void mma_f16(float* c, const unsigned* a, const unsigned* b) {
    asm volatile(
        "mma.sync.aligned.m16n8k16.row.col.f32.f16.f16.f32 "
        "{%0,%1,%2,%3}, {%4,%5,%6,%7}, {%8,%9}, {%0,%1,%2,%3};\n"
        : "+f"(c[0]), "+f"(c[1]), "+f"(c[2]), "+f"(c[3])
        : "r"(a[0]), "r"(a[1]), "r"(a[2]), "r"(a[3]), "r"(b[0]), "r"(b[1]));
}
#define LDSM_X4(r0, r1, r2, r3, addr) \
    asm volatile("ldmatrix.sync.aligned.m8n8.x4.shared.b16 {%0,%1,%2,%3}, [%4];" \
        : "=r"(r0), "=r"(r1), "=r"(r2), "=r"(r3) : "r"(addr))
__device__ __forceinline__ void cp16(unsigned dst, const void* src) {
    asm volatile("cp.async.ca.shared.global [%0], [%1], 16;\n" :: "r"(dst), "l"(src));
}
__device__ __forceinline__ void cp_commit() { asm volatile("cp.async.commit_group;\n"); }
template <int N>
__device__ __forceinline__ void cp_wait() {
    asm volatile("cp.async.wait_group %0;\n" :: "n"(N));
}

// ---------------- fused fp16 GEMM + in-kernel certification ----------------
// score(i,k) = ||e_k||^2 - 2 * x_i . e_k  (fp16 inputs, fp32 accumulate)
// fp16-score noise sigma ~0.011 (max ~0.05). If the per-row fp16 top-2 gap
// exceeds TAU=0.25, the fp16 argmin IS the exact argmin; otherwise the row
// goes to the exact full-scan fallback.
#define GBM 128
#define GBN 128
#define AROWB 528               // (256 + 8 pad) halfs = 528 bytes per row
#define ABYTES (GBM * AROWB)    // 67584
#define BBYTES (GBN * AROWB)    // 67584
#define SMEM_GEMM (ABYTES + 2 * BBYTES)   // 202752
#define NT (K_N / GBN)          // 32

__global__ __launch_bounds__(512, 1)
void k_gemm_top2(const __half* __restrict__ xh, const __half* __restrict__ ebh) {
    extern __shared__ __align__(16) unsigned char raw[];
    __shared__ float sEn[K_N];            // full enorm table, written once
    __shared__ float sS1[GBM][4], sS2[GBM][4];
    __shared__ int   sK1[GBM][4], sK2[GBM][4];

    const int tid = threadIdx.x;
    const int m0 = blockIdx.x * GBM;
    const int warp = tid >> 5, lane = tid & 31;
    const int wm = warp >> 2, wn = warp & 3;   // 4x4 warp grid, warp tile 32x32
    const int g = lane >> 2, q = lane & 3;

    const unsigned sA = (unsigned)__cvta_generic_to_shared(raw);
    const unsigned sB0 = sA + ABYTES;

    for (int i = tid; i < K_N; i += 512) sEn[i] = g_enorm[i];

    // ldmatrix lane offsets
    const unsigned a_lane_off = (unsigned)((lane & 15) * AROWB + ((lane >> 4) << 4));
    const unsigned b_lane_off =
        (unsigned)(((lane & 7) + ((lane & 16) >> 1)) * AROWB + ((lane & 8) << 1));

    // ---- load A (whole 128 x 256 tile) once ----
    #pragma unroll
    for (int i = tid; i < GBM * 32; i += 512) {
        int r = i >> 5, c8 = i & 31;
        cp16(sA + r * AROWB + c8 * 16, xh + (m0 + r) * D_N + c8 * 8);
    }
    cp_commit();
    // ---- load B tile 0 ----
    #pragma unroll
    for (int i = tid; i < GBN * 32; i += 512) {
        int r = i >> 5, c8 = i & 31;
        cp16(sB0 + r * AROWB + c8 * 16, ebh + r * D_N + c8 * 8);
    }
    cp_commit();

    float t1s[4], t2s[4];
    unsigned pk[4];
    #pragma unroll
    for (int i = 0; i < 4; i++) { t1s[i] = 3.4e38f; t2s[i] = 3.4e38f; pk[i] = 0; }

    for (int t = 0; t < NT; t++) {
        const unsigned bb = sB0 + (t & 1) * BBYTES;
        if (t + 1 < NT) {
            const __half* src = ebh + (t + 1) * GBN * D_N;
            unsigned nb = sB0 + ((t + 1) & 1) * BBYTES;
            #pragma unroll
            for (int i = tid; i < GBN * 32; i += 512) {
                int r = i >> 5, c8 = i & 31;
                cp16(nb + r * AROWB + c8 * 16, src + r * D_N + c8 * 8);
            }
            cp_commit();
            cp_wait<1>();
        } else {
            cp_wait<0>();
        }
        __syncthreads();

        float acc[2][4][4];
        #pragma unroll
        for (int a = 0; a < 2; a++)
            #pragma unroll
            for (int b = 0; b < 4; b++)
                #pragma unroll
                for (int c = 0; c < 4; c++) acc[a][b][c] = 0.0f;

        // full-K inner loop: no barriers, 16 unrolled steps
        #pragma unroll
        for (int k0 = 0; k0 < D_N; k0 += 16) {
            unsigned a[2][4], b[2][4];
            #pragma unroll
            for (int mf = 0; mf < 2; mf++) {
                unsigned addr = sA + (wm * 32 + mf * 16) * AROWB + a_lane_off + k0 * 2;
                LDSM_X4(a[mf][0], a[mf][1], a[mf][2], a[mf][3], addr);
            }
            #pragma unroll
            for (int pr = 0; pr < 2; pr++) {
                unsigned addr = bb + (wn * 32 + pr * 16) * AROWB + b_lane_off + k0 * 2;
                LDSM_X4(b[pr][0], b[pr][1], b[pr][2], b[pr][3], addr);
            }
            #pragma unroll
            for (int mf = 0; mf < 2; mf++)
                #pragma unroll
                for (int nf = 0; nf < 4; nf++)
                    mma_f16(acc[mf][nf], a[mf], &b[nf >> 1][(nf & 1) * 2]);
        }
        __syncthreads();   // done reading B[t&1] before its reload at t+2

        // fold scores into per-thread top-2
        const int n0 = t * GBN;
        #pragma unroll
        for (int nf = 0; nf < 4; nf++) {
            #pragma unroll
            for (int e = 0; e < 2; e++) {
                int col = wn * 32 + nf * 8 + 2 * q + e;
                int k = n0 + col;
                float en = sEn[k];
                #pragma unroll
                for (int mf = 0; mf < 2; mf++) {
                    #pragma unroll
                    for (int h = 0; h < 2; h++) {
                        float s = fmaf(-2.0f, acc[mf][nf][h * 2 + e], en);
                        int rid = mf * 2 + h;
                        if (s < t1s[rid]) {
                            t2s[rid] = t1s[rid];
                            t1s[rid] = s;
                            pk[rid] = ((pk[rid] & 0xffffu) << 16) | (unsigned)k;
                        } else if (s < t2s[rid]) {
                            t2s[rid] = s;
                            pk[rid] = (pk[rid] & 0xffffu) | ((unsigned)k << 16);
                        }
                    }
                }
            }
        }
    }

    // ---- in-warp merge of top-2 across the 4 q-lanes sharing each row ----
    #pragma unroll
    for (int rid = 0; rid < 4; rid++) {
        #pragma unroll
        for (int off = 1; off <= 2; off <<= 1) {
            float o1 = __shfl_xor_sync(0xffffffffu, t1s[rid], off);
            float o2 = __shfl_xor_sync(0xffffffffu, t2s[rid], off);
            unsigned op = __shfl_xor_sync(0xffffffffu, pk[rid], off);
            int ok1 = (int)(op & 0xffffu), ok2 = (int)(op >> 16);
            float s1 = t1s[rid], s2 = t2s[rid];
            int k1 = (int)(pk[rid] & 0xffffu), k2 = (int)(pk[rid] >> 16);
            float n1, n2; int nk1, nk2;
            bool ob = (o1 < s1) || (o1 == s1 && ok1 < k1);
            if (ob) {
                n1 = o1; nk1 = ok1;
                bool tb = (s1 < o2) || (s1 == o2 && k1 < ok2);
                if (tb) { n2 = s1; nk2 = k1; } else { n2 = o2; nk2 = ok2; }
            } else {
                n1 = s1; nk1 = k1;
                bool tb = (o1 < s2) || (o1 == s2 && ok1 < k2);
                if (tb) { n2 = o1; nk2 = ok1; } else { n2 = s2; nk2 = k2; }
            }
            t1s[rid] = n1; t2s[rid] = n2;
            pk[rid] = (unsigned)nk1 | ((unsigned)nk2 << 16);
        }
    }
    if (q == 0) {
        #pragma unroll
        for (int rid = 0; rid < 4; rid++) {
            int mf = rid >> 1, h = rid & 1;
            int rl = wm * 32 + mf * 16 + h * 8 + g;
            sS1[rl][wn] = t1s[rid]; sK1[rl][wn] = (int)(pk[rid] & 0xffffu);
            sS2[rl][wn] = t2s[rid]; sK2[rl][wn] = (int)(pk[rid] >> 16);
        }
    }
    __syncthreads();
    // ---- final cross-warp merge + certification (one thread per row) ----
    if (tid < GBM) {
        float b1 = 3.4e38f, b2 = 3.4e38f; int bk = 1 << 30;
        #pragma unroll
        for (int w = 0; w < 4; w++) {
            float s1 = sS1[tid][w]; int kk1 = sK1[tid][w];
            float s2 = sS2[tid][w]; int kk2 = sK2[tid][w];
            if (s1 < b1 || (s1 == b1 && kk1 < bk)) { b2 = b1; b1 = s1; bk = kk1; }
            else if (s1 < b2) b2 = s1;
            if (s2 < b1 || (s2 == b1 && kk2 < bk)) { b2 = b1; b1 = s2; bk = kk2; }
            else if (s2 < b2) b2 = s2;
        }
        int row = m0 + tid;
        g_idx[row] = bk;
        if (b2 - b1 < TAU) {               // not certified -> exact full scan
            int pos = atomicAdd(&g_nfall, 1);
            g_fall[pos] = row;
        }
    }
}

// ---------------- full exact scan for flagged rows -------------------------
__global__ __launch_bounds__(256)
void k_fallback(const float* __restrict__ x, const float* __restrict__ embed) {
    __shared__ float xs[D_N];
    __shared__ float rS[8];
    __shared__ int   rK[8];
    int tid = threadIdx.x, lane = tid & 31, warp = tid >> 5;
    int n = g_nfall;
    for (int w = blockIdx.x; w < n; w += gridDim.x) {
        int row = g_fall[w];
        __syncthreads();
        xs[tid] = x[row * D_N + tid];
        __syncthreads();

        float acc[16];
        #pragma unroll
        for (int j = 0; j < 16; j++) acc[j] = 0.0f;
        for (int d = 0; d < D_N; d++) {
            float xd = xs[d];
            const float* er = embed + d * K_N + tid;
            #pragma unroll
            for (int j = 0; j < 16; j++)
                acc[j] = fmaf(xd, er[j * 256], acc[j]);
        }
        float bs = 3.4e38f; int bk = 1 << 30;
        #pragma unroll
        for (int j = 0; j < 16; j++) {
            int k = tid + j * 256;
            float s = fmaf(-2.0f, acc[j], g_enorm[k]);
            if (s < bs || (s == bs && k < bk)) { bs = s; bk = k; }
        }
        #pragma unroll
        for (int o = 16; o > 0; o >>= 1) {
            float os = __shfl_down_sync(0xffffffffu, bs, o);
            int   ok = __shfl_down_sync(0xffffffffu, bk, o);
            if (os < bs || (os == bs && ok < bk)) { bs = os; bk = ok; }
        }
        if (lane == 0) { rS[warp] = bs; rK[warp] = bk; }
        __syncthreads();
        if (tid == 0) {
            float fbs = rS[0]; int fbk = rK[0];
            #pragma unroll
            for (int t = 1; t < 8; t++) {
                if (rS[t] < fbs || (rS[t] == fbs && rK[t] < fbk)) {
                    fbs = rS[t]; fbk = rK[t];
                }
            }
            g_idx[row] = fbk;
        }
    }
}

// ---------------- quantize + STE + loss + histogram + scatter-add ---------
__global__ __launch_bounds__(256)
void k_quant(const float* __restrict__ x, float* __restrict__ out) {
    __shared__ float blk_loss;
    if (threadIdx.x == 0) blk_loss = 0.0f;
    __syncthreads();

    int warp = threadIdx.x >> 5, lane = threadIdx.x & 31;
    int row = blockIdx.x * 8 + warp;
    int k = g_idx[row];
    const float4* xr = reinterpret_cast<const float4*>(x + row * D_N);
    const float4* er = reinterpret_cast<const float4*>(g_embedT + k * D_N);
    float4* outr = reinterpret_cast<float4*>(out + OFF_Q + row * D_N);
    float lacc = 0.0f;

    #pragma unroll
    for (int it = 0; it < 2; it++) {
        int c4 = lane * 2 + it;
        float4 xv = xr[c4];
        float4 ev = er[c4];
        float d0 = ev.x - xv.x, d1 = ev.y - xv.y, d2 = ev.z - xv.z, d3 = ev.w - xv.w;
        outr[c4] = make_float4(xv.x + d0, xv.y + d1, xv.z + d2, xv.w + d3);
        lacc = fmaf(d0, d0, lacc); lacc = fmaf(d1, d1, lacc);
        lacc = fmaf(d2, d2, lacc); lacc = fmaf(d3, d3, lacc);
        int d = c4 * 4;
        atomicAdd(&g_sumT[k * D_N + d + 0], xv.x);
        atomicAdd(&g_sumT[k * D_N + d + 1], xv.y);
        atomicAdd(&g_sumT[k * D_N + d + 2], xv.z);
        atomicAdd(&g_sumT[k * D_N + d + 3], xv.w);
    }
    #pragma unroll
    for (int o = 16; o > 0; o >>= 1) lacc += __shfl_down_sync(0xffffffffu, lacc, o);
    if (lane == 0) {
        atomicAdd(&blk_loss, lacc);
        atomicAdd(&g_counts[k], 1.0f);
        out[OFF_IDX + row] = (float)k;
    }
    __syncthreads();
    if (threadIdx.x == 0) atomicAdd(&g_scalars[0], blk_loss);
}

// ---------------- new_cluster_size + reductions ---------------------------
__global__ void k_stats(const float* __restrict__ cluster_size,
                        float* __restrict__ out) {
    __shared__ float sSum[256], sSmall[256];
    int tid = threadIdx.x;
    int k = blockIdx.x * 256 + tid;
    float ncs = fmaf(DECAYF, cluster_size[k], OMDECAYF * g_counts[k]);
    out[OFF_CS + k] = ncs;
    sSum[tid] = ncs;
    sSmall[tid] = (ncs < 1.0f) ? 1.0f : 0.0f;
    __syncthreads();
    for (int o = 128; o > 0; o >>= 1) {
        if (tid < o) { sSum[tid] += sSum[tid + o]; sSmall[tid] += sSmall[tid + o]; }
        __syncthreads();
    }
    if (tid == 0) {
        atomicAdd(&g_scalars[1], sSum[0]);
        atomicAdd(&g_scalars[2], sSmall[0]);
    }
}

// ---------------- finalize: new_embed + scalars ---------------------------
__global__ void k_final(const float* __restrict__ embed_avg,
                        float* __restrict__ out) {
    int i = blockIdx.x * blockDim.x + threadIdx.x;
    if (i == 0) {
        out[OFF_NS]   = g_scalars[2];
        out[OFF_LOSS] = g_scalars[0] * (1.0f / ((float)B_N * (float)D_N));
    }
    if (i < D_N * K_N) {
        int k = i & (K_N - 1);
        int d = i >> 12;
        float ncs = out[OFF_CS + k];
        float n = g_scalars[1];
        float cs = (ncs + EPSF) / (n + (float)K_N * EPSF) * n;
        float navg = fmaf(DECAYF, embed_avg[i], OMDECAYF * g_sumT[k * D_N + d]);
        out[OFF_E + i] = navg / cs;
    }
}

// ---------------- launch ---------------------------------------------------
extern "C" void kernel_launch(void* const* d_in, const int* in_sizes, int n_in,
                              void* d_out, int out_size) {
    const float* x            = (const float*)d_in[0];  // [B, D]
    const float* embed        = (const float*)d_in[1];  // [D, K]
    const float* cluster_size = (const float*)d_in[2];  // [K]
    const float* embed_avg    = (const float*)d_in[3];  // [D, K]
    float* out = (float*)d_out;
    (void)in_sizes; (void)n_in; (void)out_size;

    static int smem_set = 0;
    if (!smem_set) {
        cudaFuncSetAttribute(k_gemm_top2,
                             cudaFuncAttributeMaxDynamicSharedMemorySize, SMEM_GEMM);
        smem_set = 1;
    }

    __half* xh;  cudaGetSymbolAddress((void**)&xh, g_xh);
    __half* ebh; cudaGetSymbolAddress((void**)&ebh, g_ebh);

    k_zero<<<(K_N * D_N + 255) / 256, 256>>>();
    k_transp<<<dim3(K_N / 32, D_N / 32), dim3(32, 8)>>>(embed);
    k_tohalf<<<B_N * D_N / 4 / 256, 256>>>(x);
    k_enorm<<<(K_N + 255) / 256, 256>>>(embed);
    k_gemm_top2<<<B_N / GBM, 512, SMEM_GEMM>>>(xh, ebh);
    k_fallback<<<1024, 256>>>(x, embed);
    k_quant<<<B_N / 8, 256>>>(x, out);
    k_stats<<<K_N / 256, 256>>>(cluster_size, out);
    k_final<<<(D_N * K_N + 255) / 256, 256>>>(embed_avg, out);
}

// round 14
// speedup vs baseline: 4.4912x; 1.1789x over previous
#include <cuda_runtime.h>
#include <cuda_fp16.h>
#include <cstdint>

// Problem constants
#define B_N 65536
#define D_N 256
#define K_N 4096
#define DECAYF 0.99f
#define OMDECAYF 0.01f
#define EPSF 1e-5f
#define TAU 0.25f

// Output layout (concatenated float32, tuple order)
#define OFF_IDX  0
#define OFF_Q    65536
#define OFF_NS   16842752
#define OFF_LOSS 16842753
#define OFF_CS   16842754
#define OFF_E    16846850

// ---------------- device scratch ----------------
__device__ float  g_sumT[K_N * D_N];     // [K,D] scatter-add of x
__device__ float  g_embedT[K_N * D_N];   // [K,D] fp32 codebook
__device__ __half g_ebh[K_N * D_N];      // [K,D] fp16 codebook (GEMM B)
__device__ __half g_xh[B_N * D_N];       // [B,D] fp16 x (GEMM A)
__device__ float  g_counts[K_N];
__device__ float  g_enorm[K_N];
__device__ int    g_idx[B_N];
__device__ int    g_fall[B_N];
__device__ int    g_nfall;
__device__ float  g_scalars[4];          // 0: loss_sum, 1: n_sum, 2: n_small

// ---------------- fused zero + x->fp16 convert -----------------------------
#define BD4 (B_N * D_N / 4)              // 4194304 float4s
__global__ void k_prep(const float* __restrict__ x) {
    int i = blockIdx.x * blockDim.x + threadIdx.x;
    if (i < BD4) {
        float4 v = reinterpret_cast<const float4*>(x)[i];
        __half2* o = reinterpret_cast<__half2*>(g_xh) + i * 2;
        o[0] = __floats2half2_rn(v.x, v.y);
        o[1] = __floats2half2_rn(v.z, v.w);
    }
    if (i < K_N * D_N) g_sumT[i] = 0.0f;
    if (i < K_N) g_counts[i] = 0.0f;
    if (i < 4) g_scalars[i] = 0.0f;
    if (i == 0) g_nfall = 0;
}

// ---------------- transpose embed [D,K] -> [K,D] (f32 + fp16) --------------
__global__ void k_transp(const float* __restrict__ embed) {
    __shared__ float t[32][33];
    int bx = blockIdx.x, by = blockIdx.y;
    int kx = bx * 32 + threadIdx.x;
    int dy = by * 32 + threadIdx.y;
    #pragma unroll
    for (int i = 0; i < 32; i += 8)
        t[threadIdx.y + i][threadIdx.x] = embed[(dy + i) * K_N + kx];
    __syncthreads();
    int k2 = bx * 32 + threadIdx.y;
    int d2 = by * 32 + threadIdx.x;
    #pragma unroll
    for (int i = 0; i < 32; i += 8) {
        float v = t[threadIdx.x][threadIdx.y + i];
        g_embedT[(k2 + i) * D_N + d2] = v;
        g_ebh[(k2 + i) * D_N + d2] = __float2half_rn(v);
    }
}

// ---------------- ||e_k||^2 (exact fp32, sequential-d order) ---------------
__global__ void k_enorm(const float* __restrict__ embed) {
    int k = blockIdx.x * blockDim.x + threadIdx.x;
    if (k >= K_N) return;
    float acc = 0.0f;
    #pragma unroll 16
    for (int d = 0; d < D_N; d++) {
        float v = embed[d * K_N + k];
        acc = fmaf(v, v, acc);
    }
    g_enorm[k] = acc;
}

// ---------------- mma / ldmatrix / cp.async helpers ------------------------
__device__ __forceinline__ void mma_f16(float* c, const unsigned* a, const unsigned* b) {
    asm volatile(
        "mma.sync.aligned.m16n8k16.row.col.f32.f16.f16.f32 "
        "{%0,%1,%2,%3}, {%4,%5,%6,%7}, {%8,%9}, {%0,%1,%2,%3};\n"
        : "+f"(c[0]), "+f"(c[1]), "+f"(c[2]), "+f"(c[3])
        : "r"(a[0]), "r"(a[1]), "r"(a[2]), "r"(a[3]), "r"(b[0]), "r"(b[1]));
}
#define LDSM_X4(r0, r1, r2, r3, addr) \
    asm volatile("ldmatrix.sync.aligned.m8n8.x4.shared.b16 {%0,%1,%2,%3}, [%4];" \
        : "=r"(r0), "=r"(r1), "=r"(r2), "=r"(r3) : "r"(addr))
__device__ __forceinline__ void cp16(unsigned dst, const void* src) {
    asm volatile("cp.async.ca.shared.global [%0], [%1], 16;\n" :: "r"(dst), "l"(src));
}
__device__ __forceinline__ void cp_commit() { asm volatile("cp.async.commit_group;\n"); }
template <int N>
__device__ __forceinline__ void cp_wait() {
    asm volatile("cp.async.wait_group %0;\n" :: "n"(N));
}
__device__ __forceinline__ void red_add_v4(float* addr, float4 v) {
    asm volatile("red.global.v4.f32.add [%0], {%1, %2, %3, %4};"
                 :: "l"(addr), "f"(v.x), "f"(v.y), "f"(v.z), "f"(v.w) : "memory");
}

// ---------------- fused fp16 GEMM + in-kernel certification ----------------
// score(i,k) = ||e_k||^2 - 2 * x_i . e_k  (fp16 inputs, fp32 accumulate)
// If the per-row fp16 top-2 gap exceeds TAU, the fp16 argmin IS the exact
// argmin; otherwise the row goes to the exact full-scan fallback.
#define GBM 128
#define GBN 128
#define AROWB 528               // (256 + 8 pad) halfs = 528 bytes per row
#define ABYTES (GBM * AROWB)    // 67584
#define BBYTES (GBN * AROWB)    // 67584
#define SMEM_GEMM (ABYTES + 2 * BBYTES)   // 202752
#define NT (K_N / GBN)          // 32

__global__ __launch_bounds__(512, 1)
void k_gemm_top2(const __half* __restrict__ xh, const __half* __restrict__ ebh) {
    extern __shared__ __align__(16) unsigned char raw[];
    __shared__ float sEn[K_N];            // full enorm table, written once
    __shared__ float sS1[GBM][4], sS2[GBM][4];
    __shared__ int   sK1[GBM][4], sK2[GBM][4];

    const int tid = threadIdx.x;
    const int m0 = blockIdx.x * GBM;
    const int warp = tid >> 5, lane = tid & 31;
    const int wm = warp >> 2, wn = warp & 3;   // 4x4 warp grid, warp tile 32x32
    const int g = lane >> 2, q = lane & 3;

    const unsigned sA = (unsigned)__cvta_generic_to_shared(raw);
    const unsigned sB0 = sA + ABYTES;

    for (int i = tid; i < K_N; i += 512) sEn[i] = g_enorm[i];

    const unsigned a_lane_off = (unsigned)((lane & 15) * AROWB + ((lane >> 4) << 4));
    const unsigned b_lane_off =
        (unsigned)(((lane & 7) + ((lane & 16) >> 1)) * AROWB + ((lane & 8) << 1));

    // ---- load A (whole 128 x 256 tile) once ----
    #pragma unroll
    for (int i = tid; i < GBM * 32; i += 512) {
        int r = i >> 5, c8 = i & 31;
        cp16(sA + r * AROWB + c8 * 16, xh + (m0 + r) * D_N + c8 * 8);
    }
    cp_commit();
    // ---- load B tile 0 ----
    #pragma unroll
    for (int i = tid; i < GBN * 32; i += 512) {
        int r = i >> 5, c8 = i & 31;
        cp16(sB0 + r * AROWB + c8 * 16, ebh + r * D_N + c8 * 8);
    }
    cp_commit();

    float t1s[4], t2s[4];
    unsigned pk[4];
    #pragma unroll
    for (int i = 0; i < 4; i++) { t1s[i] = 3.4e38f; t2s[i] = 3.4e38f; pk[i] = 0; }

    for (int t = 0; t < NT; t++) {
        const unsigned bb = sB0 + (t & 1) * BBYTES;
        if (t + 1 < NT) {
            const __half* src = ebh + (t + 1) * GBN * D_N;
            unsigned nb = sB0 + ((t + 1) & 1) * BBYTES;
            #pragma unroll
            for (int i = tid; i < GBN * 32; i += 512) {
                int r = i >> 5, c8 = i & 31;
                cp16(nb + r * AROWB + c8 * 16, src + r * D_N + c8 * 8);
            }
            cp_commit();
            cp_wait<1>();
        } else {
            cp_wait<0>();
        }
        __syncthreads();

        float acc[2][4][4];
        #pragma unroll
        for (int a = 0; a < 2; a++)
            #pragma unroll
            for (int b = 0; b < 4; b++)
                #pragma unroll
                for (int c = 0; c < 4; c++) acc[a][b][c] = 0.0f;

        #pragma unroll
        for (int k0 = 0; k0 < D_N; k0 += 16) {
            unsigned a[2][4], b[2][4];
            #pragma unroll
            for (int mf = 0; mf < 2; mf++) {
                unsigned addr = sA + (wm * 32 + mf * 16) * AROWB + a_lane_off + k0 * 2;
                LDSM_X4(a[mf][0], a[mf][1], a[mf][2], a[mf][3], addr);
            }
            #pragma unroll
            for (int pr = 0; pr < 2; pr++) {
                unsigned addr = bb + (wn * 32 + pr * 16) * AROWB + b_lane_off + k0 * 2;
                LDSM_X4(b[pr][0], b[pr][1], b[pr][2], b[pr][3], addr);
            }
            #pragma unroll
            for (int mf = 0; mf < 2; mf++)
                #pragma unroll
                for (int nf = 0; nf < 4; nf++)
                    mma_f16(acc[mf][nf], a[mf], &b[nf >> 1][(nf & 1) * 2]);
        }
        __syncthreads();

        const int n0 = t * GBN;
        #pragma unroll
        for (int nf = 0; nf < 4; nf++) {
            #pragma unroll
            for (int e = 0; e < 2; e++) {
                int col = wn * 32 + nf * 8 + 2 * q + e;
                int k = n0 + col;
                float en = sEn[k];
                #pragma unroll
                for (int mf = 0; mf < 2; mf++) {
                    #pragma unroll
                    for (int h = 0; h < 2; h++) {
                        float s = fmaf(-2.0f, acc[mf][nf][h * 2 + e], en);
                        int rid = mf * 2 + h;
                        if (s < t1s[rid]) {
                            t2s[rid] = t1s[rid];
                            t1s[rid] = s;
                            pk[rid] = ((pk[rid] & 0xffffu) << 16) | (unsigned)k;
                        } else if (s < t2s[rid]) {
                            t2s[rid] = s;
                            pk[rid] = (pk[rid] & 0xffffu) | ((unsigned)k << 16);
                        }
                    }
                }
            }
        }
    }

    // ---- in-warp merge of top-2 across the 4 q-lanes sharing each row ----
    #pragma unroll
    for (int rid = 0; rid < 4; rid++) {
        #pragma unroll
        for (int off = 1; off <= 2; off <<= 1) {
            float o1 = __shfl_xor_sync(0xffffffffu, t1s[rid], off);
            float o2 = __shfl_xor_sync(0xffffffffu, t2s[rid], off);
            unsigned op = __shfl_xor_sync(0xffffffffu, pk[rid], off);
            int ok1 = (int)(op & 0xffffu), ok2 = (int)(op >> 16);
            float s1 = t1s[rid], s2 = t2s[rid];
            int k1 = (int)(pk[rid] & 0xffffu), k2 = (int)(pk[rid] >> 16);
            float n1, n2; int nk1, nk2;
            bool ob = (o1 < s1) || (o1 == s1 && ok1 < k1);
            if (ob) {
                n1 = o1; nk1 = ok1;
                bool tb = (s1 < o2) || (s1 == o2 && k1 < ok2);
                if (tb) { n2 = s1; nk2 = k1; } else { n2 = o2; nk2 = ok2; }
            } else {
                n1 = s1; nk1 = k1;
                bool tb = (o1 < s2) || (o1 == s2 && ok1 < k2);
                if (tb) { n2 = o1; nk2 = ok1; } else { n2 = s2; nk2 = k2; }
            }
            t1s[rid] = n1; t2s[rid] = n2;
            pk[rid] = (unsigned)nk1 | ((unsigned)nk2 << 16);
        }
    }
    if (q == 0) {
        #pragma unroll
        for (int rid = 0; rid < 4; rid++) {
            int mf = rid >> 1, h = rid & 1;
            int rl = wm * 32 + mf * 16 + h * 8 + g;
            sS1[rl][wn] = t1s[rid]; sK1[rl][wn] = (int)(pk[rid] & 0xffffu);
            sS2[rl][wn] = t2s[rid]; sK2[rl][wn] = (int)(pk[rid] >> 16);
        }
    }
    __syncthreads();
    // ---- final cross-warp merge + certification (one thread per row) ----
    if (tid < GBM) {
        float b1 = 3.4e38f, b2 = 3.4e38f; int bk = 1 << 30;
        #pragma unroll
        for (int w = 0; w < 4; w++) {
            float s1 = sS1[tid][w]; int kk1 = sK1[tid][w];
            float s2 = sS2[tid][w]; int kk2 = sK2[tid][w];
            if (s1 < b1 || (s1 == b1 && kk1 < bk)) { b2 = b1; b1 = s1; bk = kk1; }
            else if (s1 < b2) b2 = s1;
            if (s2 < b1 || (s2 == b1 && kk2 < bk)) { b2 = b1; b1 = s2; bk = kk2; }
            else if (s2 < b2) b2 = s2;
        }
        int row = m0 + tid;
        g_idx[row] = bk;
        if (b2 - b1 < TAU) {
            int pos = atomicAdd(&g_nfall, 1);
            g_fall[pos] = row;
        }
    }
}

// ---------------- full exact scan for flagged rows -------------------------
__global__ __launch_bounds__(256)
void k_fallback(const float* __restrict__ x, const float* __restrict__ embed) {
    __shared__ float xs[D_N];
    __shared__ float rS[8];
    __shared__ int   rK[8];
    int tid = threadIdx.x, lane = tid & 31, warp = tid >> 5;
    int n = g_nfall;
    for (int w = blockIdx.x; w < n; w += gridDim.x) {
        int row = g_fall[w];
        __syncthreads();
        xs[tid] = x[row * D_N + tid];
        __syncthreads();

        float acc[16];
        #pragma unroll
        for (int j = 0; j < 16; j++) acc[j] = 0.0f;
        for (int d = 0; d < D_N; d++) {
            float xd = xs[d];
            const float* er = embed + d * K_N + tid;
            #pragma unroll
            for (int j = 0; j < 16; j++)
                acc[j] = fmaf(xd, er[j * 256], acc[j]);
        }
        float bs = 3.4e38f; int bk = 1 << 30;
        #pragma unroll
        for (int j = 0; j < 16; j++) {
            int k = tid + j * 256;
            float s = fmaf(-2.0f, acc[j], g_enorm[k]);
            if (s < bs || (s == bs && k < bk)) { bs = s; bk = k; }
        }
        #pragma unroll
        for (int o = 16; o > 0; o >>= 1) {
            float os = __shfl_down_sync(0xffffffffu, bs, o);
            int   ok = __shfl_down_sync(0xffffffffu, bk, o);
            if (os < bs || (os == bs && ok < bk)) { bs = os; bk = ok; }
        }
        if (lane == 0) { rS[warp] = bs; rK[warp] = bk; }
        __syncthreads();
        if (tid == 0) {
            float fbs = rS[0]; int fbk = rK[0];
            #pragma unroll
            for (int t = 1; t < 8; t++) {
                if (rS[t] < fbs || (rS[t] == fbs && rK[t] < fbk)) {
                    fbs = rS[t]; fbk = rK[t];
                }
            }
            g_idx[row] = fbk;
        }
    }
}

// ---------------- quantize + STE + loss + histogram + scatter-add ---------
__global__ __launch_bounds__(256)
void k_quant(const float* __restrict__ x, float* __restrict__ out) {
    __shared__ float blk_loss;
    if (threadIdx.x == 0) blk_loss = 0.0f;
    __syncthreads();

    int warp = threadIdx.x >> 5, lane = threadIdx.x & 31;
    int row = blockIdx.x * 8 + warp;
    int k = g_idx[row];
    const float4* xr = reinterpret_cast<const float4*>(x + row * D_N);
    const float4* er = reinterpret_cast<const float4*>(g_embedT + k * D_N);
    float4* outr = reinterpret_cast<float4*>(out + OFF_Q + row * D_N);
    float lacc = 0.0f;

    #pragma unroll
    for (int it = 0; it < 2; it++) {
        int c4 = lane * 2 + it;
        float4 xv = xr[c4];
        float4 ev = er[c4];
        float d0 = ev.x - xv.x, d1 = ev.y - xv.y, d2 = ev.z - xv.z, d3 = ev.w - xv.w;
        outr[c4] = make_float4(xv.x + d0, xv.y + d1, xv.z + d2, xv.w + d3);
        lacc = fmaf(d0, d0, lacc); lacc = fmaf(d1, d1, lacc);
        lacc = fmaf(d2, d2, lacc); lacc = fmaf(d3, d3, lacc);
        red_add_v4(&g_sumT[k * D_N + c4 * 4], xv);   // vector scatter-add
    }
    #pragma unroll
    for (int o = 16; o > 0; o >>= 1) lacc += __shfl_down_sync(0xffffffffu, lacc, o);
    if (lane == 0) {
        atomicAdd(&blk_loss, lacc);
        atomicAdd(&g_counts[k], 1.0f);
        out[OFF_IDX + row] = (float)k;
    }
    __syncthreads();
    if (threadIdx.x == 0) atomicAdd(&g_scalars[0], blk_loss);
}

// ---------------- new_cluster_size + reductions ---------------------------
__global__ void k_stats(const float* __restrict__ cluster_size,
                        float* __restrict__ out) {
    __shared__ float sSum[256], sSmall[256];
    int tid = threadIdx.x;
    int k = blockIdx.x * 256 + tid;
    float ncs = fmaf(DECAYF, cluster_size[k], OMDECAYF * g_counts[k]);
    out[OFF_CS + k] = ncs;
    sSum[tid] = ncs;
    sSmall[tid] = (ncs < 1.0f) ? 1.0f : 0.0f;
    __syncthreads();
    for (int o = 128; o > 0; o >>= 1) {
        if (tid < o) { sSum[tid] += sSum[tid + o]; sSmall[tid] += sSmall[tid + o]; }
        __syncthreads();
    }
    if (tid == 0) {
        atomicAdd(&g_scalars[1], sSum[0]);
        atomicAdd(&g_scalars[2], sSmall[0]);
    }
}

// ---------------- finalize: new_embed + scalars ---------------------------
__global__ void k_final(const float* __restrict__ embed_avg,
                        float* __restrict__ out) {
    int i = blockIdx.x * blockDim.x + threadIdx.x;
    if (i == 0) {
        out[OFF_NS]   = g_scalars[2];
        out[OFF_LOSS] = g_scalars[0] * (1.0f / ((float)B_N * (float)D_N));
    }
    if (i < D_N * K_N) {
        int k = i & (K_N - 1);
        int d = i >> 12;
        float ncs = out[OFF_CS + k];
        float n = g_scalars[1];
        float cs = (ncs + EPSF) / (n + (float)K_N * EPSF) * n;
        float navg = fmaf(DECAYF, embed_avg[i], OMDECAYF * g_sumT[k * D_N + d]);
        out[OFF_E + i] = navg / cs;
    }
}

// ---------------- launch ---------------------------------------------------
extern "C" void kernel_launch(void* const* d_in, const int* in_sizes, int n_in,
                              void* d_out, int out_size) {
    const float* x            = (const float*)d_in[0];  // [B, D]
    const float* embed        = (const float*)d_in[1];  // [D, K]
    const float* cluster_size = (const float*)d_in[2];  // [K]
    const float* embed_avg    = (const float*)d_in[3];  // [D, K]
    float* out = (float*)d_out;
    (void)in_sizes; (void)n_in; (void)out_size;

    static int smem_set = 0;
    if (!smem_set) {
        cudaFuncSetAttribute(k_gemm_top2,
                             cudaFuncAttributeMaxDynamicSharedMemorySize, SMEM_GEMM);
        smem_set = 1;
    }

    __half* xh;  cudaGetSymbolAddress((void**)&xh, g_xh);
    __half* ebh; cudaGetSymbolAddress((void**)&ebh, g_ebh);

    k_prep<<<(BD4 + 255) / 256, 256>>>(x);
    k_transp<<<dim3(K_N / 32, D_N / 32), dim3(32, 8)>>>(embed);
    k_enorm<<<(K_N + 255) / 256, 256>>>(embed);
    k_gemm_top2<<<B_N / GBM, 512, SMEM_GEMM>>>(xh, ebh);
    k_fallback<<<1024, 256>>>(x, embed);
    k_quant<<<B_N / 8, 256>>>(x, out);
    k_stats<<<K_N / 256, 256>>>(cluster_size, out);
    k_final<<<(D_N * K_N + 255) / 256, 256>>>(embed_avg, out);
}

// round 15
// speedup vs baseline: 4.5142x; 1.0051x over previous
#include <cuda_runtime.h>
#include <cuda_fp16.h>
#include <cstdint>

// Problem constants
#define B_N 65536
#define D_N 256
#define K_N 4096
#define DECAYF 0.99f
#define OMDECAYF 0.01f
#define EPSF 1e-5f
#define TAU 0.25f

// Output layout (concatenated float32, tuple order)
#define OFF_IDX  0
#define OFF_Q    65536
#define OFF_NS   16842752
#define OFF_LOSS 16842753
#define OFF_CS   16842754
#define OFF_E    16846850

// ---------------- device scratch ----------------
__device__ float  g_sumT[K_N * D_N];     // [K,D] scatter-add of x
__device__ float  g_embedT[K_N * D_N];   // [K,D] fp32 codebook
__device__ __half g_ebh[K_N * D_N];      // [K,D] fp16 codebook (GEMM B)
__device__ __half g_xh[B_N * D_N];       // [B,D] fp16 x (GEMM A)
__device__ float  g_counts[K_N];
__device__ float  g_enorm[K_N];
__device__ int    g_idx[B_N];
__device__ int    g_fall[B_N];
__device__ int    g_nfall;
__device__ float  g_scalars[4];          // 0: loss_sum, 1: n_sum, 2: n_small

// ---------------- fused zero + x->fp16 convert -----------------------------
#define BD4 (B_N * D_N / 4)              // 4194304 float4s
__global__ void k_prep(const float* __restrict__ x) {
    int i = blockIdx.x * blockDim.x + threadIdx.x;
    if (i < BD4) {
        float4 v = reinterpret_cast<const float4*>(x)[i];
        __half2* o = reinterpret_cast<__half2*>(g_xh) + i * 2;
        o[0] = __floats2half2_rn(v.x, v.y);
        o[1] = __floats2half2_rn(v.z, v.w);
    }
    if (i < K_N * D_N) g_sumT[i] = 0.0f;
    if (i < K_N) g_counts[i] = 0.0f;
    if (i < 4) g_scalars[i] = 0.0f;
    if (i == 0) g_nfall = 0;
}

// ---------------- transpose embed [D,K] -> [K,D] (f32 + fp16) --------------
__global__ void k_transp(const float* __restrict__ embed) {
    __shared__ float t[32][33];
    int bx = blockIdx.x, by = blockIdx.y;
    int kx = bx * 32 + threadIdx.x;
    int dy = by * 32 + threadIdx.y;
    #pragma unroll
    for (int i = 0; i < 32; i += 8)
        t[threadIdx.y + i][threadIdx.x] = embed[(dy + i) * K_N + kx];
    __syncthreads();
    int k2 = bx * 32 + threadIdx.y;
    int d2 = by * 32 + threadIdx.x;
    #pragma unroll
    for (int i = 0; i < 32; i += 8) {
        float v = t[threadIdx.x][threadIdx.y + i];
        g_embedT[(k2 + i) * D_N + d2] = v;
        g_ebh[(k2 + i) * D_N + d2] = __float2half_rn(v);
    }
}

// ---------------- ||e_k||^2 (exact fp32, sequential-d order) ---------------
// 32-thread blocks spread across 128 SMs for aggregate MLP; the per-thread
// accumulation order is IDENTICAL to previous rounds (bit-identical enorm).
__global__ void k_enorm(const float* __restrict__ embed) {
    int k = blockIdx.x * blockDim.x + threadIdx.x;
    if (k >= K_N) return;
    float acc = 0.0f;
    #pragma unroll 16
    for (int d = 0; d < D_N; d++) {
        float v = embed[d * K_N + k];
        acc = fmaf(v, v, acc);
    }
    g_enorm[k] = acc;
}

// ---------------- mma / ldmatrix / cp.async helpers ------------------------
__device__ __forceinline__ void mma_f16(float* c, const unsigned* a, const unsigned* b) {
    asm volatile(
        "mma.sync.aligned.m16n8k16.row.col.f32.f16.f16.f32 "
        "{%0,%1,%2,%3}, {%4,%5,%6,%7}, {%8,%9}, {%0,%1,%2,%3};\n"
        : "+f"(c[0]), "+f"(c[1]), "+f"(c[2]), "+f"(c[3])
        : "r"(a[0]), "r"(a[1]), "r"(a[2]), "r"(a[3]), "r"(b[0]), "r"(b[1]));
}
#define LDSM_X4(r0, r1, r2, r3, addr) \
    asm volatile("ldmatrix.sync.aligned.m8n8.x4.shared.b16 {%0,%1,%2,%3}, [%4];" \
        : "=r"(r0), "=r"(r1), "=r"(r2), "=r"(r3) : "r"(addr))
__device__ __forceinline__ void cp16(unsigned dst, const void* src) {
    asm volatile("cp.async.ca.shared.global [%0], [%1], 16;\n" :: "r"(dst), "l"(src));
}
__device__ __forceinline__ void cp_commit() { asm volatile("cp.async.commit_group;\n"); }
template <int N>
__device__ __forceinline__ void cp_wait() {
    asm volatile("cp.async.wait_group %0;\n" :: "n"(N));
}
__device__ __forceinline__ void red_add_v4(float* addr, float4 v) {
    asm volatile("red.global.v4.f32.add [%0], {%1, %2, %3, %4};"
                 :: "l"(addr), "f"(v.x), "f"(v.y), "f"(v.z), "f"(v.w) : "memory");
}

// ---------------- fused fp16 GEMM + in-kernel certification ----------------
// score(i,k) = ||e_k||^2 - 2 * x_i . e_k  (fp16 inputs, fp32 accumulate)
// If the per-row fp16 top-2 gap exceeds TAU, the fp16 argmin IS the exact
// argmin; otherwise the row goes to the exact full-scan fallback.
#define GBM 128
#define GBN 128
#define AROWB 528               // (256 + 8 pad) halfs = 528 bytes per row
#define ABYTES (GBM * AROWB)    // 67584
#define BBYTES (GBN * AROWB)    // 67584
#define SMEM_GEMM (ABYTES + 2 * BBYTES)   // 202752
#define NT (K_N / GBN)          // 32

__global__ __launch_bounds__(512, 1)
void k_gemm_top2(const __half* __restrict__ xh, const __half* __restrict__ ebh) {
    extern __shared__ __align__(16) unsigned char raw[];
    __shared__ float sEn[K_N];            // full enorm table, written once
    __shared__ float sS1[GBM][4], sS2[GBM][4];
    __shared__ int   sK1[GBM][4], sK2[GBM][4];

    const int tid = threadIdx.x;
    const int m0 = blockIdx.x * GBM;
    const int warp = tid >> 5, lane = tid & 31;
    const int wm = warp >> 2, wn = warp & 3;   // 4x4 warp grid, warp tile 32x32
    const int g = lane >> 2, q = lane & 3;

    const unsigned sA = (unsigned)__cvta_generic_to_shared(raw);
    const unsigned sB0 = sA + ABYTES;

    for (int i = tid; i < K_N; i += 512) sEn[i] = g_enorm[i];

    const unsigned a_lane_off = (unsigned)((lane & 15) * AROWB + ((lane >> 4) << 4));
    const unsigned b_lane_off =
        (unsigned)(((lane & 7) + ((lane & 16) >> 1)) * AROWB + ((lane & 8) << 1));

    // ---- load A (whole 128 x 256 tile) once ----
    #pragma unroll
    for (int i = tid; i < GBM * 32; i += 512) {
        int r = i >> 5, c8 = i & 31;
        cp16(sA + r * AROWB + c8 * 16, xh + (m0 + r) * D_N + c8 * 8);
    }
    cp_commit();
    // ---- load B tile 0 ----
    #pragma unroll
    for (int i = tid; i < GBN * 32; i += 512) {
        int r = i >> 5, c8 = i & 31;
        cp16(sB0 + r * AROWB + c8 * 16, ebh + r * D_N + c8 * 8);
    }
    cp_commit();

    float t1s[4], t2s[4];
    unsigned pk[4];
    #pragma unroll
    for (int i = 0; i < 4; i++) { t1s[i] = 3.4e38f; t2s[i] = 3.4e38f; pk[i] = 0; }

    for (int t = 0; t < NT; t++) {
        const unsigned bb = sB0 + (t & 1) * BBYTES;
        if (t + 1 < NT) {
            const __half* src = ebh + (t + 1) * GBN * D_N;
            unsigned nb = sB0 + ((t + 1) & 1) * BBYTES;
            #pragma unroll
            for (int i = tid; i < GBN * 32; i += 512) {
                int r = i >> 5, c8 = i & 31;
                cp16(nb + r * AROWB + c8 * 16, src + r * D_N + c8 * 8);
            }
            cp_commit();
            cp_wait<1>();
        } else {
            cp_wait<0>();
        }
        __syncthreads();

        float acc[2][4][4];
        #pragma unroll
        for (int a = 0; a < 2; a++)
            #pragma unroll
            for (int b = 0; b < 4; b++)
                #pragma unroll
                for (int c = 0; c < 4; c++) acc[a][b][c] = 0.0f;

        #pragma unroll
        for (int k0 = 0; k0 < D_N; k0 += 16) {
            unsigned a[2][4], b[2][4];
            #pragma unroll
            for (int mf = 0; mf < 2; mf++) {
                unsigned addr = sA + (wm * 32 + mf * 16) * AROWB + a_lane_off + k0 * 2;
                LDSM_X4(a[mf][0], a[mf][1], a[mf][2], a[mf][3], addr);
            }
            #pragma unroll
            for (int pr = 0; pr < 2; pr++) {
                unsigned addr = bb + (wn * 32 + pr * 16) * AROWB + b_lane_off + k0 * 2;
                LDSM_X4(b[pr][0], b[pr][1], b[pr][2], b[pr][3], addr);
            }
            #pragma unroll
            for (int mf = 0; mf < 2; mf++)
                #pragma unroll
                for (int nf = 0; nf < 4; nf++)
                    mma_f16(acc[mf][nf], a[mf], &b[nf >> 1][(nf & 1) * 2]);
        }
        __syncthreads();

        const int n0 = t * GBN;
        #pragma unroll
        for (int nf = 0; nf < 4; nf++) {
            #pragma unroll
            for (int e = 0; e < 2; e++) {
                int col = wn * 32 + nf * 8 + 2 * q + e;
                int k = n0 + col;
                float en = sEn[k];
                #pragma unroll
                for (int mf = 0; mf < 2; mf++) {
                    #pragma unroll
                    for (int h = 0; h < 2; h++) {
                        float s = fmaf(-2.0f, acc[mf][nf][h * 2 + e], en);
                        int rid = mf * 2 + h;
                        if (s < t1s[rid]) {
                            t2s[rid] = t1s[rid];
                            t1s[rid] = s;
                            pk[rid] = ((pk[rid] & 0xffffu) << 16) | (unsigned)k;
                        } else if (s < t2s[rid]) {
                            t2s[rid] = s;
                            pk[rid] = (pk[rid] & 0xffffu) | ((unsigned)k << 16);
                        }
                    }
                }
            }
        }
    }

    // ---- in-warp merge of top-2 across the 4 q-lanes sharing each row ----
    #pragma unroll
    for (int rid = 0; rid < 4; rid++) {
        #pragma unroll
        for (int off = 1; off <= 2; off <<= 1) {
            float o1 = __shfl_xor_sync(0xffffffffu, t1s[rid], off);
            float o2 = __shfl_xor_sync(0xffffffffu, t2s[rid], off);
            unsigned op = __shfl_xor_sync(0xffffffffu, pk[rid], off);
            int ok1 = (int)(op & 0xffffu), ok2 = (int)(op >> 16);
            float s1 = t1s[rid], s2 = t2s[rid];
            int k1 = (int)(pk[rid] & 0xffffu), k2 = (int)(pk[rid] >> 16);
            float n1, n2; int nk1, nk2;
            bool ob = (o1 < s1) || (o1 == s1 && ok1 < k1);
            if (ob) {
                n1 = o1; nk1 = ok1;
                bool tb = (s1 < o2) || (s1 == o2 && k1 < ok2);
                if (tb) { n2 = s1; nk2 = k1; } else { n2 = o2; nk2 = ok2; }
            } else {
                n1 = s1; nk1 = k1;
                bool tb = (o1 < s2) || (o1 == s2 && ok1 < k2);
                if (tb) { n2 = o1; nk2 = ok1; } else { n2 = s2; nk2 = k2; }
            }
            t1s[rid] = n1; t2s[rid] = n2;
            pk[rid] = (unsigned)nk1 | ((unsigned)nk2 << 16);
        }
    }
    if (q == 0) {
        #pragma unroll
        for (int rid = 0; rid < 4; rid++) {
            int mf = rid >> 1, h = rid & 1;
            int rl = wm * 32 + mf * 16 + h * 8 + g;
            sS1[rl][wn] = t1s[rid]; sK1[rl][wn] = (int)(pk[rid] & 0xffffu);
            sS2[rl][wn] = t2s[rid]; sK2[rl][wn] = (int)(pk[rid] >> 16);
        }
    }
    __syncthreads();
    // ---- final cross-warp merge + certification (one thread per row) ----
    if (tid < GBM) {
        float b1 = 3.4e38f, b2 = 3.4e38f; int bk = 1 << 30;
        #pragma unroll
        for (int w = 0; w < 4; w++) {
            float s1 = sS1[tid][w]; int kk1 = sK1[tid][w];
            float s2 = sS2[tid][w]; int kk2 = sK2[tid][w];
            if (s1 < b1 || (s1 == b1 && kk1 < bk)) { b2 = b1; b1 = s1; bk = kk1; }
            else if (s1 < b2) b2 = s1;
            if (s2 < b1 || (s2 == b1 && kk2 < bk)) { b2 = b1; b1 = s2; bk = kk2; }
            else if (s2 < b2) b2 = s2;
        }
        int row = m0 + tid;
        g_idx[row] = bk;
        if (b2 - b1 < TAU) {
            int pos = atomicAdd(&g_nfall, 1);
            g_fall[pos] = row;
        }
    }
}

// ---------------- full exact scan for flagged rows -------------------------
__global__ __launch_bounds__(256)
void k_fallback(const float* __restrict__ x, const float* __restrict__ embed) {
    __shared__ float xs[D_N];
    __shared__ float rS[8];
    __shared__ int   rK[8];
    int tid = threadIdx.x, lane = tid & 31, warp = tid >> 5;
    int n = g_nfall;
    for (int w = blockIdx.x; w < n; w += gridDim.x) {
        int row = g_fall[w];
        __syncthreads();
        xs[tid] = x[row * D_N + tid];
        __syncthreads();

        float acc[16];
        #pragma unroll
        for (int j = 0; j < 16; j++) acc[j] = 0.0f;
        for (int d = 0; d < D_N; d++) {
            float xd = xs[d];
            const float* er = embed + d * K_N + tid;
            #pragma unroll
            for (int j = 0; j < 16; j++)
                acc[j] = fmaf(xd, er[j * 256], acc[j]);
        }
        float bs = 3.4e38f; int bk = 1 << 30;
        #pragma unroll
        for (int j = 0; j < 16; j++) {
            int k = tid + j * 256;
            float s = fmaf(-2.0f, acc[j], g_enorm[k]);
            if (s < bs || (s == bs && k < bk)) { bs = s; bk = k; }
        }
        #pragma unroll
        for (int o = 16; o > 0; o >>= 1) {
            float os = __shfl_down_sync(0xffffffffu, bs, o);
            int   ok = __shfl_down_sync(0xffffffffu, bk, o);
            if (os < bs || (os == bs && ok < bk)) { bs = os; bk = ok; }
        }
        if (lane == 0) { rS[warp] = bs; rK[warp] = bk; }
        __syncthreads();
        if (tid == 0) {
            float fbs = rS[0]; int fbk = rK[0];
            #pragma unroll
            for (int t = 1; t < 8; t++) {
                if (rS[t] < fbs || (rS[t] == fbs && rK[t] < fbk)) {
                    fbs = rS[t]; fbk = rK[t];
                }
            }
            g_idx[row] = fbk;
        }
    }
}

// ---------------- quantize + STE + loss + histogram + scatter-add ---------
// Two rows per warp; all 8 float4 loads issued up front for MLP.
__global__ __launch_bounds__(256)
void k_quant(const float* __restrict__ x, float* __restrict__ out) {
    __shared__ float blk_loss;
    if (threadIdx.x == 0) blk_loss = 0.0f;
    __syncthreads();

    int warp = threadIdx.x >> 5, lane = threadIdx.x & 31;
    int rowA = blockIdx.x * 16 + warp * 2;
    int rowB = rowA + 1;
    int kA = g_idx[rowA], kB = g_idx[rowB];

    const float4* xrA = reinterpret_cast<const float4*>(x + rowA * D_N);
    const float4* xrB = reinterpret_cast<const float4*>(x + rowB * D_N);
    const float4* erA = reinterpret_cast<const float4*>(g_embedT + kA * D_N);
    const float4* erB = reinterpret_cast<const float4*>(g_embedT + kB * D_N);
    int c0 = lane * 2, c1 = lane * 2 + 1;

    float4 xa0 = xrA[c0], xa1 = xrA[c1];
    float4 xb0 = xrB[c0], xb1 = xrB[c1];
    float4 ea0 = erA[c0], ea1 = erA[c1];
    float4 eb0 = erB[c0], eb1 = erB[c1];

    float4* outA = reinterpret_cast<float4*>(out + OFF_Q + rowA * D_N);
    float4* outB = reinterpret_cast<float4*>(out + OFF_Q + rowB * D_N);

    float lacc = 0.0f;
    {
        float d0 = ea0.x - xa0.x, d1 = ea0.y - xa0.y, d2 = ea0.z - xa0.z, d3 = ea0.w - xa0.w;
        outA[c0] = make_float4(xa0.x + d0, xa0.y + d1, xa0.z + d2, xa0.w + d3);
        lacc = fmaf(d0, d0, lacc); lacc = fmaf(d1, d1, lacc);
        lacc = fmaf(d2, d2, lacc); lacc = fmaf(d3, d3, lacc);
        red_add_v4(&g_sumT[kA * D_N + c0 * 4], xa0);
        float e0 = ea1.x - xa1.x, e1 = ea1.y - xa1.y, e2 = ea1.z - xa1.z, e3 = ea1.w - xa1.w;
        outA[c1] = make_float4(xa1.x + e0, xa1.y + e1, xa1.z + e2, xa1.w + e3);
        lacc = fmaf(e0, e0, lacc); lacc = fmaf(e1, e1, lacc);
        lacc = fmaf(e2, e2, lacc); lacc = fmaf(e3, e3, lacc);
        red_add_v4(&g_sumT[kA * D_N + c1 * 4], xa1);
    }
    {
        float d0 = eb0.x - xb0.x, d1 = eb0.y - xb0.y, d2 = eb0.z - xb0.z, d3 = eb0.w - xb0.w;
        outB[c0] = make_float4(xb0.x + d0, xb0.y + d1, xb0.z + d2, xb0.w + d3);
        lacc = fmaf(d0, d0, lacc); lacc = fmaf(d1, d1, lacc);
        lacc = fmaf(d2, d2, lacc); lacc = fmaf(d3, d3, lacc);
        red_add_v4(&g_sumT[kB * D_N + c0 * 4], xb0);
        float e0 = eb1.x - xb1.x, e1 = eb1.y - xb1.y, e2 = eb1.z - xb1.z, e3 = eb1.w - xb1.w;
        outB[c1] = make_float4(xb1.x + e0, xb1.y + e1, xb1.z + e2, xb1.w + e3);
        lacc = fmaf(e0, e0, lacc); lacc = fmaf(e1, e1, lacc);
        lacc = fmaf(e2, e2, lacc); lacc = fmaf(e3, e3, lacc);
        red_add_v4(&g_sumT[kB * D_N + c1 * 4], xb1);
    }

    #pragma unroll
    for (int o = 16; o > 0; o >>= 1) lacc += __shfl_down_sync(0xffffffffu, lacc, o);
    if (lane == 0) {
        atomicAdd(&blk_loss, lacc);
        atomicAdd(&g_counts[kA], 1.0f);
        atomicAdd(&g_counts[kB], 1.0f);
        out[OFF_IDX + rowA] = (float)kA;
        out[OFF_IDX + rowB] = (float)kB;
    }
    __syncthreads();
    if (threadIdx.x == 0) atomicAdd(&g_scalars[0], blk_loss);
}

// ---------------- new_cluster_size + reductions ---------------------------
__global__ void k_stats(const float* __restrict__ cluster_size,
                        float* __restrict__ out) {
    __shared__ float sSum[256], sSmall[256];
    int tid = threadIdx.x;
    int k = blockIdx.x * 256 + tid;
    float ncs = fmaf(DECAYF, cluster_size[k], OMDECAYF * g_counts[k]);
    out[OFF_CS + k] = ncs;
    sSum[tid] = ncs;
    sSmall[tid] = (ncs < 1.0f) ? 1.0f : 0.0f;
    __syncthreads();
    for (int o = 128; o > 0; o >>= 1) {
        if (tid < o) { sSum[tid] += sSum[tid + o]; sSmall[tid] += sSmall[tid + o]; }
        __syncthreads();
    }
    if (tid == 0) {
        atomicAdd(&g_scalars[1], sSum[0]);
        atomicAdd(&g_scalars[2], sSmall[0]);
    }
}

// ---------------- finalize: new_embed + scalars ---------------------------
__global__ void k_final(const float* __restrict__ embed_avg,
                        float* __restrict__ out) {
    int i = blockIdx.x * blockDim.x + threadIdx.x;
    if (i == 0) {
        out[OFF_NS]   = g_scalars[2];
        out[OFF_LOSS] = g_scalars[0] * (1.0f / ((float)B_N * (float)D_N));
    }
    if (i < D_N * K_N) {
        int k = i & (K_N - 1);
        int d = i >> 12;
        float ncs = out[OFF_CS + k];
        float n = g_scalars[1];
        float cs = (ncs + EPSF) / (n + (float)K_N * EPSF) * n;
        float navg = fmaf(DECAYF, embed_avg[i], OMDECAYF * g_sumT[k * D_N + d]);
        out[OFF_E + i] = navg / cs;
    }
}

// ---------------- launch ---------------------------------------------------
extern "C" void kernel_launch(void* const* d_in, const int* in_sizes, int n_in,
                              void* d_out, int out_size) {
    const float* x            = (const float*)d_in[0];  // [B, D]
    const float* embed        = (const float*)d_in[1];  // [D, K]
    const float* cluster_size = (const float*)d_in[2];  // [K]
    const float* embed_avg    = (const float*)d_in[3];  // [D, K]
    float* out = (float*)d_out;
    (void)in_sizes; (void)n_in; (void)out_size;

    static int smem_set = 0;
    if (!smem_set) {
        cudaFuncSetAttribute(k_gemm_top2,
                             cudaFuncAttributeMaxDynamicSharedMemorySize, SMEM_GEMM);
        smem_set = 1;
    }

    __half* xh;  cudaGetSymbolAddress((void**)&xh, g_xh);
    __half* ebh; cudaGetSymbolAddress((void**)&ebh, g_ebh);

    k_prep<<<(BD4 + 255) / 256, 256>>>(x);
    k_transp<<<dim3(K_N / 32, D_N / 32), dim3(32, 8)>>>(embed);
    k_enorm<<<K_N / 32, 32>>>(embed);
    k_gemm_top2<<<B_N / GBM, 512, SMEM_GEMM>>>(xh, ebh);
    k_fallback<<<1024, 256>>>(x, embed);
    k_quant<<<B_N / 16, 256>>>(x, out);
    k_stats<<<K_N / 256, 256>>>(cluster_size, out);
    k_final<<<(D_N * K_N + 255) / 256, 256>>>(embed_avg, out);
}